// round 6
// baseline (speedup 1.0000x reference)
#include <cuda_runtime.h>
#include <math.h>

// Problem constants
#define BSX   2
#define QL    64
#define KLN   64
#define NH    8
#define DKV   64
#define INNER 512
#define VOC   4096
#define NBH   16          // BSX * NH
#define VSPL  64          // v-range splits (64 v each) for argmax kernel

// Masks (all scratch arrays are power-of-2 element counts)
#define M_PROJ 0xFFFFu     // 65536
#define M_DICT 0x3FFFFu    // 262144
#define M_AB   0x3FFFFFu   // 4194304
#define M_NRM  0x3FFu      // 1024
#define M_G    0xFFFFu     // 65536
#define M_P    0x3FFFFFu   // 4194304

// ---------------- scratch (device globals; no allocation allowed) -------------
__device__ float g_qproj[BSX * QL * INNER];        // [b][q][e]       65536
__device__ float g_kproj[BSX * KLN * INNER];       // [b][k][e]       65536
__device__ float g_dnT[DKV * VOC];                 // l2 dict, [d][v] 262144
__device__ float g_dp[VOC * DKV];                  // LN(dict)@O      262144
__device__ float g_A[NBH * QL * VOC];              // [bh][q][v]      4194304
__device__ float g_Bm[NBH * KLN * VOC];            // [bh][k][v]      4194304
__device__ float g_nq[NBH * QL];                   // ||qp||^2        1024
__device__ float g_nk[NBH * KLN];                  //                 1024
__device__ float g_G[NBH * QL * KLN];              // <qp,kp>         65536
__device__ float g_pv[NBH * QL * KLN * VSPL];      // partial max     4194304

// ---------------- K0: dict preprocessing (l2norm(T) + LN@O) -------------------
__global__ void k0_dict(const float* __restrict__ dict,
                        const float* __restrict__ vg,
                        const float* __restrict__ vb,
                        const float* __restrict__ O) {
    int l = threadIdx.x;                               // 0..31
    int r = blockIdx.x * blockDim.y + threadIdx.y;     // 0..4095
    float x0 = dict[(r * DKV + l) & M_DICT];
    float x1 = dict[(r * DKV + 32 + l) & M_DICT];

    float s = x0 * x0 + x1 * x1;
    #pragma unroll
    for (int o = 16; o > 0; o >>= 1) s += __shfl_xor_sync(0xffffffffu, s, o);
    float inv = rsqrtf(fmaxf(s, 1e-12f));
    // transposed normalized dict: g_dnT[d][v]
    g_dnT[(l * VOC + r) & M_DICT]        = x0 * inv;
    g_dnT[((l + 32) * VOC + r) & M_DICT] = x1 * inv;

    float m = x0 + x1;
    #pragma unroll
    for (int o = 16; o > 0; o >>= 1) m += __shfl_xor_sync(0xffffffffu, m, o);
    m *= (1.0f / 64.0f);
    float d0 = x0 - m, d1 = x1 - m;
    float v = d0 * d0 + d1 * d1;
    #pragma unroll
    for (int o = 16; o > 0; o >>= 1) v += __shfl_xor_sync(0xffffffffu, v, o);
    v *= (1.0f / 64.0f);
    float rs = rsqrtf(v + 1e-6f);
    float ln0 = d0 * rs * vg[l & 63]      + vb[l & 63];
    float ln1 = d1 * rs * vg[(l + 32) & 63] + vb[(l + 32) & 63];

    float a0 = 0.f, a1 = 0.f;
    #pragma unroll
    for (int d2 = 0; d2 < 32; d2++) {
        float t = __shfl_sync(0xffffffffu, ln0, d2);
        a0 += t * O[(d2 * 64 + l) & 4095];
        a1 += t * O[(d2 * 64 + 32 + l) & 4095];
    }
    #pragma unroll
    for (int d2 = 0; d2 < 32; d2++) {
        float t = __shfl_sync(0xffffffffu, ln1, d2);
        a0 += t * O[((32 + d2) * 64 + l) & 4095];
        a1 += t * O[((32 + d2) * 64 + 32 + l) & 4095];
    }
    g_dp[(r * DKV + l) & M_DICT]      = a0;
    g_dp[(r * DKV + 32 + l) & M_DICT] = a1;
}

// ---------------- K1: q_proj / k_proj GEMM ------------------------------------
__global__ void k1_proj(const float* __restrict__ q, const float* __restrict__ k,
                        const float* __restrict__ qpe, const float* __restrict__ kpe,
                        const float* __restrict__ wi) {
    __shared__ __align__(16) float xs[8][INNER];
    int side = blockIdx.z;
    const float* xin = side ? k   : q;
    const float* pin = side ? kpe : qpe;
    const float* W   = wi + side * (INNER * INNER);
    float* out = side ? g_kproj : g_qproj;
    int m0 = blockIdx.y * 8;
    int tid = threadIdx.x;                             // 128 threads
    for (int i = tid; i < 8 * INNER; i += 128) {
        int r = i >> 9, d = i & 511;
        int gidx = ((m0 + r) * INNER + d) & M_PROJ;
        xs[r][d] = xin[gidx] + pin[gidx];
    }
    __syncthreads();
    int e = blockIdx.x * 128 + tid;                    // 0..511
    float acc[8] = {};
    for (int d = 0; d < INNER; d += 4) {
        float w0 = W[((d + 0) * INNER + e) & 0x3FFFF];
        float w1 = W[((d + 1) * INNER + e) & 0x3FFFF];
        float w2 = W[((d + 2) * INNER + e) & 0x3FFFF];
        float w3 = W[((d + 3) * INNER + e) & 0x3FFFF];
        #pragma unroll
        for (int r = 0; r < 8; r++) {
            float4 xv = *(const float4*)&xs[r][d];
            acc[r] += xv.x * w0 + xv.y * w1 + xv.z * w2 + xv.w * w3;
        }
    }
    #pragma unroll
    for (int r = 0; r < 8; r++)
        out[((m0 + r) * INNER + e) & M_PROJ] = acc[r];
}

// ---------------- K1c: per-head Gram matrix + row norms -----------------------
__global__ void k1c_gram() {
    __shared__ float qs[64][65];
    __shared__ float ks[64][65];
    int bh = blockIdx.x;                               // 0..15
    int b = bh >> 3, h = bh & 7;
    int tid = threadIdx.x;                             // 256
    for (int i = tid; i < 4096; i += 256) {
        int r = i >> 6, d = i & 63;
        qs[r][d] = g_qproj[((b * 64 + r) * INNER + h * 64 + d) & M_PROJ];
        ks[r][d] = g_kproj[((b * 64 + r) * INNER + h * 64 + d) & M_PROJ];
    }
    __syncthreads();
    int qq = tid >> 2;
    int kb = (tid & 3) * 16;
    float acc[16] = {};
    for (int d = 0; d < 64; d++) {
        float a = qs[qq][d];
        #pragma unroll
        for (int j = 0; j < 16; j++) acc[j] += a * ks[kb + j][d];
    }
    #pragma unroll
    for (int j = 0; j < 16; j++)
        g_G[((bh * 64 + qq) * 64 + kb + j) & M_G] = acc[j];
    if (tid < 64) {
        float s = 0.f;
        #pragma unroll 8
        for (int d = 0; d < 64; d++) { float x = qs[tid][d]; s += x * x; }
        g_nq[(bh * 64 + tid) & M_NRM] = s;
    } else if (tid < 128) {
        int r = tid - 64;
        float s = 0.f;
        #pragma unroll 8
        for (int d = 0; d < 64; d++) { float x = ks[r][d]; s += x * x; }
        g_nk[(bh * 64 + r) & M_NRM] = s;
    }
}

// ---------------- K2: A = qp_head @ dnT, B = kp_head @ dnT --------------------
// block: 64 rows x 64 v; 64 threads; per-thread 8 rows x 8 v (interleaved rows)
__global__ void k2_ab() {
    __shared__ __align__(16) float xs[64][65];         // [row][d]
    __shared__ __align__(16) float dst[64][68];        // [d][v]
    int vc   = blockIdx.x;                             // 0..63 (64-v chunk)
    int bh   = blockIdx.y;                             // 0..15
    int side = blockIdx.z;
    int b = bh >> 3, h = bh & 7;
    int v0 = vc * 64;
    const float* xin = side ? g_kproj : g_qproj;
    float* out = side ? g_Bm : g_A;
    int tid = threadIdx.x;                             // 64

    // xs: 64 rows x 64 d (float4 gmem load, scalar smem stores)
    for (int i = tid; i < 64 * 16; i += 64) {
        int r = i >> 4, d4 = (i & 15) * 4;
        int g = ((b * 64 + r) * INNER + h * 64 + d4) & (M_PROJ & ~3u);
        float4 vv = *(const float4*)&xin[g];
        xs[r][d4 + 0] = vv.x; xs[r][d4 + 1] = vv.y;
        xs[r][d4 + 2] = vv.z; xs[r][d4 + 3] = vv.w;
    }
    // dst: straight copy of pre-transposed dict rows (no transpose needed)
    for (int i = tid; i < 64 * 16; i += 64) {
        int d = i >> 4, m4 = (i & 15) * 4;
        int g = (d * VOC + v0 + m4) & (M_DICT & ~3u);
        *(float4*)&dst[d][m4] = *(const float4*)&g_dnT[g];
    }
    __syncthreads();

    int tv = tid & 7, tr = tid >> 3;                   // 8 v-groups x 8 row-groups
    float acc[8][8] = {};
    #pragma unroll 2
    for (int d = 0; d < 64; d++) {
        float4 dv0 = *(const float4*)&dst[d][tv * 8];
        float4 dv1 = *(const float4*)&dst[d][tv * 8 + 4];
        #pragma unroll
        for (int i = 0; i < 8; i++) {
            float a = xs[tr + 8 * i][d];               // interleaved rows
            acc[i][0] += a * dv0.x; acc[i][1] += a * dv0.y;
            acc[i][2] += a * dv0.z; acc[i][3] += a * dv0.w;
            acc[i][4] += a * dv1.x; acc[i][5] += a * dv1.y;
            acc[i][6] += a * dv1.z; acc[i][7] += a * dv1.w;
        }
    }
    #pragma unroll
    for (int i = 0; i < 8; i++) {
        int row = tr + 8 * i;
        int base = ((bh * 64 + row) * VOC + v0 + tv * 8) & (M_AB & ~3u);
        *(float4*)&out[base]     = make_float4(acc[i][0], acc[i][1], acc[i][2], acc[i][3]);
        *(float4*)&out[base + 4] = make_float4(acc[i][4], acc[i][5], acc[i][6], acc[i][7]);
    }
}

// ---------------- K3: partial max_v (A[q,v] + B[k,v]) — VALUES ONLY -----------
// block: (bh, vs of 64 v); 64 threads; per-thread 8q x 8k; FADD+FMNMX only
__global__ void k3_maxv() {
    __shared__ float As[64][65];
    __shared__ float Bs[64][65];
    int vs = blockIdx.x;                               // 0..63
    int bh = blockIdx.y;                               // 0..15
    int tid = threadIdx.x;                             // 64
    int vb = vs * 64;

    for (int i = tid; i < 64 * 16; i += 64) {
        int r = i >> 4, m4 = (i & 15) * 4;
        float4 av = *(const float4*)&g_A [((bh * 64 + r) * VOC + vb + m4) & (M_AB & ~3u)];
        float4 bv = *(const float4*)&g_Bm[((bh * 64 + r) * VOC + vb + m4) & (M_AB & ~3u)];
        As[r][m4 + 0] = av.x; As[r][m4 + 1] = av.y; As[r][m4 + 2] = av.z; As[r][m4 + 3] = av.w;
        Bs[r][m4 + 0] = bv.x; Bs[r][m4 + 1] = bv.y; Bs[r][m4 + 2] = bv.z; Bs[r][m4 + 3] = bv.w;
    }
    __syncthreads();

    int tq = tid & 7, tk = tid >> 3;                   // q rows tq+8i, k rows tk+8j
    float best[8][8];
    #pragma unroll
    for (int i = 0; i < 8; i++)
        #pragma unroll
        for (int j = 0; j < 8; j++) best[i][j] = -3.402823466e38f;

    #pragma unroll 2
    for (int v = 0; v < 64; v++) {
        float a[8], bb[8];
        #pragma unroll
        for (int i = 0; i < 8; i++) { a[i] = As[tq + 8 * i][v]; bb[i] = Bs[tk + 8 * i][v]; }
        #pragma unroll
        for (int i = 0; i < 8; i++)
            #pragma unroll
            for (int j = 0; j < 8; j++)
                best[i][j] = fmaxf(best[i][j], a[i] + bb[j]);   // FADD + FMNMX
    }
    #pragma unroll
    for (int i = 0; i < 8; i++)
        #pragma unroll
        for (int j = 0; j < 8; j++) {
            int q = tq + 8 * i, kk = tk + 8 * j;
            int pair = (bh * 64 + q) * 64 + kk;
            g_pv[(pair * VSPL + vs) & M_P] = best[i][j];
        }
}

// ---------------- K4: merge + index recovery + weighted sum + final LN --------
__global__ void k4_final(const float* __restrict__ lng, const float* __restrict__ lnb,
                         float* __restrict__ out, int n_out) {
    __shared__ float sws[64];
    __shared__ int   sid[64];
    __shared__ float sred[64];
    int idx = blockIdx.x;                              // 0..1023 = (b,q,h)
    int b = idx >> 9, q = (idx >> 3) & 63, h = idx & 7;
    int bh = b * 8 + h;
    int t = threadIdx.x;                               // 64
    int kk = t;
    int pair = (bh * 64 + q) * 64 + kk;

    // merge 64 partial maxima; track FIRST split achieving the max
    float bv = -3.402823466e38f; int sp = 0;
    #pragma unroll 8
    for (int p = 0; p < VSPL; p++) {
        float v = g_pv[(pair * VSPL + p) & M_P];
        if (v > bv) { bv = v; sp = p; }
    }
    // recover index: first v in winning split with bit-identical sum
    int rowA = ((bh * 64 + q)  * VOC + sp * 64);
    int rowB = ((bh * 64 + kk) * VOC + sp * 64);
    int bi = -1;
    #pragma unroll 8
    for (int v = 0; v < 64; v++) {
        float c = g_A[(rowA + v) & M_AB] + g_Bm[(rowB + v) & M_AB];
        bool hit = (c == bv) && (bi < 0);
        bi = hit ? (sp * 64 + v) : bi;
    }
    if (bi < 0) bi = 0;                                // unreachable; safety

    float n2 = g_nq[(bh * 64 + q) & M_NRM] + g_nk[(bh * 64 + kk) & M_NRM]
             + 2.0f * g_G[((bh * 64 + q) * 64 + kk) & M_G];
    float ws = bv * rsqrtf(fmaxf(n2, 1e-12f));
    int oidx = ((b * 64 + q) * 64 + kk) * 8 + h;
    if (65536 + oidx < n_out)  out[65536  + oidx] = (float)bi;  // out_ids
    if (131072 + oidx < n_out) out[131072 + oidx] = ws;         // r3_scores
    sws[t] = ws; sid[t] = bi;
    __syncthreads();
    int e = t;
    float acc = 0.f;
    #pragma unroll 4
    for (int j = 0; j < 64; j++)
        acc += sws[j] * g_dp[(sid[j] * DKV + e) & M_DICT];
    acc *= (1.0f / 64.0f);
    sred[t] = acc; __syncthreads();
    #pragma unroll
    for (int s = 32; s > 0; s >>= 1) { if (t < s) sred[t] += sred[t + s]; __syncthreads(); }
    float mean = sred[0] * (1.0f / 64.0f);
    __syncthreads();
    float diff = acc - mean;
    sred[t] = diff * diff; __syncthreads();
    #pragma unroll
    for (int s = 32; s > 0; s >>= 1) { if (t < s) sred[t] += sred[t + s]; __syncthreads(); }
    float var = sred[0] * (1.0f / 64.0f);
    float r = diff * rsqrtf(var + 1e-6f) * lng[e & 63] + lnb[e & 63];
    int widx = (bh * 64 + q) * 64 + e;
    if (widx < n_out) out[widx] = r;                   // [b][h][q][e]
}

// ---------------- fallback: zero-fill output (diagnostic, never crashes) ------
__global__ void kz_zero(float* __restrict__ out, int n_out) {
    int i = blockIdx.x * 256 + threadIdx.x;
    if (i < n_out) out[i] = 0.0f;
}

// ---------------- launch ------------------------------------------------------
static bool size_ok(int got, int need_elems) {
    return got == need_elems || got == need_elems * 4;   // elements or bytes
}

extern "C" void kernel_launch(void* const* d_in, const int* in_sizes, int n_in,
                              void* d_out, int out_size) {
    int n_out = out_size;
    if (n_out == 65536 * 4 || n_out == 196608 * 4) n_out >>= 2;
    if (n_out < 0) n_out = 0;
    float* out = (float*)d_out;

    const int SZ_BIG = BSX * QL * INNER;       // 65536
    const int SZ_WI  = 2 * INNER * INNER;      // 524288
    const int SZ_DI  = VOC * DKV;              // 262144
    const int SZ_OW  = DKV * DKV;              // 4096
    const int SZ_V   = DKV;                    // 64

    const float *query = 0, *key = 0, *qpe = 0, *kpe = 0, *wi = 0, *dict = 0,
                *ow = 0, *vg = 0, *vb = 0, *lg = 0, *lb = 0;
    bool mapped = false;

    if (n_in >= 11) {
        const int sig[11] = {SZ_BIG, SZ_BIG, SZ_BIG, SZ_BIG, SZ_WI, SZ_DI,
                             SZ_V, SZ_V, SZ_OW, SZ_V, SZ_V};
        bool ok = true;
        for (int i = 0; i < 11; i++) ok = ok && size_ok(in_sizes[i], sig[i]);
        if (ok) {
            query = (const float*)d_in[0];  key = (const float*)d_in[1];
            qpe   = (const float*)d_in[2];  kpe = (const float*)d_in[3];
            wi    = (const float*)d_in[4];  dict = (const float*)d_in[5];
            vg    = (const float*)d_in[6];  vb  = (const float*)d_in[7];
            ow    = (const float*)d_in[8];  lg  = (const float*)d_in[9];
            lb    = (const float*)d_in[10];
            mapped = true;
        }
        if (!mapped) {
            const int alp[11] = {SZ_BIG, SZ_BIG, SZ_V, SZ_V, SZ_BIG, SZ_BIG,
                                 SZ_DI, SZ_V, SZ_V, SZ_OW, SZ_WI};
            bool ok2 = true;
            for (int i = 0; i < 11; i++) ok2 = ok2 && size_ok(in_sizes[i], alp[i]);
            if (ok2) {
                key  = (const float*)d_in[0];  kpe = (const float*)d_in[1];
                lb   = (const float*)d_in[2];  lg  = (const float*)d_in[3];
                qpe  = (const float*)d_in[4];  query = (const float*)d_in[5];
                dict = (const float*)d_in[6];  vb  = (const float*)d_in[7];
                vg   = (const float*)d_in[8];  ow  = (const float*)d_in[9];
                wi   = (const float*)d_in[10];
                mapped = true;
            }
        }
    }

    if (!mapped) {
        if (n_out > 0) kz_zero<<<(n_out + 255) / 256, 256>>>(out, n_out);
        return;
    }

    k0_dict <<<512, dim3(32, 8)>>>(dict, vg, vb, ow);
    k1_proj <<<dim3(4, 16, 2), 128>>>(query, key, qpe, kpe, wi);
    k1c_gram<<<16, 256>>>();
    k2_ab   <<<dim3(64, 16, 2), 64>>>();
    k3_maxv <<<dim3(64, 16), 64>>>();
    k4_final<<<1024, 64>>>(lg, lb, out, n_out);
}

// round 7
// speedup vs baseline: 1.0981x; 1.0981x over previous
#include <cuda_runtime.h>
#include <math.h>

// Problem constants
#define BSX   2
#define QL    64
#define KLN   64
#define NH    8
#define DKV   64
#define INNER 512
#define VOC   4096
#define NBH   16          // BSX * NH
#define VSPL  64          // v-range splits (64 v each) for argmax kernel

// Masks (all scratch arrays are power-of-2 element counts)
#define M_PROJ 0xFFFFu     // 65536
#define M_DICT 0x3FFFFu    // 262144
#define M_AB   0x3FFFFFu   // 4194304
#define M_NRM  0x3FFu      // 1024
#define M_G    0xFFFFu     // 65536
#define M_P    0x3FFFFFu   // 4194304

// ---------------- scratch (device globals; no allocation allowed) -------------
__device__ float g_qproj[BSX * QL * INNER];        // [b][q][e]       65536
__device__ float g_kproj[BSX * KLN * INNER];       // [b][k][e]       65536
__device__ float g_dnT[DKV * VOC];                 // l2 dict, [d][v] 262144
__device__ float g_dp[VOC * DKV];                  // LN(dict)@O      262144
__device__ float g_A[NBH * QL * VOC];              // [bh][q][v]      4194304
__device__ float g_Bm[NBH * KLN * VOC];            // [bh][k][v]      4194304
__device__ float g_nq[NBH * QL];                   // ||qp||^2        1024
__device__ float g_nk[NBH * KLN];                  //                 1024
__device__ float g_G[NBH * QL * KLN];              // <qp,kp>         65536
__device__ float g_pv[NBH * QL * KLN * VSPL];      // partial max     4194304

// ---------------- K0: dict preprocessing (l2norm(T) + LN@O) -------------------
__global__ void k0_dict(const float* __restrict__ dict,
                        const float* __restrict__ vg,
                        const float* __restrict__ vb,
                        const float* __restrict__ O) {
    int l = threadIdx.x;                               // 0..31
    int r = blockIdx.x * blockDim.y + threadIdx.y;     // 0..4095
    float x0 = dict[(r * DKV + l) & M_DICT];
    float x1 = dict[(r * DKV + 32 + l) & M_DICT];

    float s = x0 * x0 + x1 * x1;
    #pragma unroll
    for (int o = 16; o > 0; o >>= 1) s += __shfl_xor_sync(0xffffffffu, s, o);
    float inv = rsqrtf(fmaxf(s, 1e-12f));
    // transposed normalized dict: g_dnT[d][v]
    g_dnT[(l * VOC + r) & M_DICT]        = x0 * inv;
    g_dnT[((l + 32) * VOC + r) & M_DICT] = x1 * inv;

    float m = x0 + x1;
    #pragma unroll
    for (int o = 16; o > 0; o >>= 1) m += __shfl_xor_sync(0xffffffffu, m, o);
    m *= (1.0f / 64.0f);
    float d0 = x0 - m, d1 = x1 - m;
    float v = d0 * d0 + d1 * d1;
    #pragma unroll
    for (int o = 16; o > 0; o >>= 1) v += __shfl_xor_sync(0xffffffffu, v, o);
    v *= (1.0f / 64.0f);
    float rs = rsqrtf(v + 1e-6f);
    float ln0 = d0 * rs * vg[l & 63]      + vb[l & 63];
    float ln1 = d1 * rs * vg[(l + 32) & 63] + vb[(l + 32) & 63];

    float a0 = 0.f, a1 = 0.f;
    #pragma unroll
    for (int d2 = 0; d2 < 32; d2++) {
        float t = __shfl_sync(0xffffffffu, ln0, d2);
        a0 += t * O[(d2 * 64 + l) & 4095];
        a1 += t * O[(d2 * 64 + 32 + l) & 4095];
    }
    #pragma unroll
    for (int d2 = 0; d2 < 32; d2++) {
        float t = __shfl_sync(0xffffffffu, ln1, d2);
        a0 += t * O[((32 + d2) * 64 + l) & 4095];
        a1 += t * O[((32 + d2) * 64 + 32 + l) & 4095];
    }
    g_dp[(r * DKV + l) & M_DICT]      = a0;
    g_dp[(r * DKV + 32 + l) & M_DICT] = a1;
}

// ---------------- K1: q_proj / k_proj GEMM ------------------------------------
__global__ void k1_proj(const float* __restrict__ q, const float* __restrict__ k,
                        const float* __restrict__ qpe, const float* __restrict__ kpe,
                        const float* __restrict__ wi) {
    __shared__ __align__(16) float xs[8][INNER];
    int side = blockIdx.z;
    const float* xin = side ? k   : q;
    const float* pin = side ? kpe : qpe;
    const float* W   = wi + side * (INNER * INNER);
    float* out = side ? g_kproj : g_qproj;
    int m0 = blockIdx.y * 8;
    int tid = threadIdx.x;                             // 128 threads
    for (int i = tid; i < 8 * INNER; i += 128) {
        int r = i >> 9, d = i & 511;
        int gidx = ((m0 + r) * INNER + d) & M_PROJ;
        xs[r][d] = xin[gidx] + pin[gidx];
    }
    __syncthreads();
    int e = blockIdx.x * 128 + tid;                    // 0..511
    float acc[8] = {};
    for (int d = 0; d < INNER; d += 4) {
        float w0 = W[((d + 0) * INNER + e) & 0x3FFFF];
        float w1 = W[((d + 1) * INNER + e) & 0x3FFFF];
        float w2 = W[((d + 2) * INNER + e) & 0x3FFFF];
        float w3 = W[((d + 3) * INNER + e) & 0x3FFFF];
        #pragma unroll
        for (int r = 0; r < 8; r++) {
            float4 xv = *(const float4*)&xs[r][d];
            acc[r] += xv.x * w0 + xv.y * w1 + xv.z * w2 + xv.w * w3;
        }
    }
    #pragma unroll
    for (int r = 0; r < 8; r++)
        out[((m0 + r) * INNER + e) & M_PROJ] = acc[r];
}

// ---------------- K1c: per-head Gram matrix + row norms -----------------------
__global__ void k1c_gram() {
    __shared__ float qs[64][65];
    __shared__ float ks[64][65];
    int bh = blockIdx.x;                               // 0..15
    int b = bh >> 3, h = bh & 7;
    int tid = threadIdx.x;                             // 256
    for (int i = tid; i < 4096; i += 256) {
        int r = i >> 6, d = i & 63;
        qs[r][d] = g_qproj[((b * 64 + r) * INNER + h * 64 + d) & M_PROJ];
        ks[r][d] = g_kproj[((b * 64 + r) * INNER + h * 64 + d) & M_PROJ];
    }
    __syncthreads();
    int qq = tid >> 2;
    int kb = (tid & 3) * 16;
    float acc[16] = {};
    for (int d = 0; d < 64; d++) {
        float a = qs[qq][d];
        #pragma unroll
        for (int j = 0; j < 16; j++) acc[j] += a * ks[kb + j][d];
    }
    #pragma unroll
    for (int j = 0; j < 16; j++)
        g_G[((bh * 64 + qq) * 64 + kb + j) & M_G] = acc[j];
    if (tid < 64) {
        float s = 0.f;
        #pragma unroll 8
        for (int d = 0; d < 64; d++) { float x = qs[tid][d]; s += x * x; }
        g_nq[(bh * 64 + tid) & M_NRM] = s;
    } else if (tid < 128) {
        int r = tid - 64;
        float s = 0.f;
        #pragma unroll 8
        for (int d = 0; d < 64; d++) { float x = ks[r][d]; s += x * x; }
        g_nk[(bh * 64 + r) & M_NRM] = s;
    }
}

// ---------------- K2: A = qp_head @ dnT, B = kp_head @ dnT --------------------
// block: 128 rows (bh-pair, shared dict slab) x 64 v; 128 threads; 8r x 8v each
__global__ void k2_ab() {
    __shared__ __align__(16) float xs[128][68];        // [row][d]
    __shared__ __align__(16) float dst[64][68];        // [d][v]
    int vc   = blockIdx.x;                             // 0..63 (64-v chunk)
    int bhp  = blockIdx.y;                             // 0..7 (bh pair)
    int side = blockIdx.z;
    int b  = bhp >> 2, hp = bhp & 3;                   // h = hp*2 + (r>=64)
    int v0 = vc * 64;
    const float* xin = side ? g_kproj : g_qproj;
    float* out = side ? g_Bm : g_A;
    int tid = threadIdx.x;                             // 128

    // xs: 128 rows x 64 d (two heads of a batch, float4 gmem loads)
    for (int i = tid; i < 128 * 16; i += 128) {
        int r = i >> 4, d4 = (i & 15) * 4;
        int h = hp * 2 + (r >> 6);
        int g = ((b * 64 + (r & 63)) * INNER + h * 64 + d4) & (M_PROJ & ~3u);
        float4 vv = *(const float4*)&xin[g];
        xs[r][d4 + 0] = vv.x; xs[r][d4 + 1] = vv.y;
        xs[r][d4 + 2] = vv.z; xs[r][d4 + 3] = vv.w;
    }
    // dst: straight copy of pre-transposed dict rows
    for (int i = tid; i < 64 * 16; i += 128) {
        int d = i >> 4, m4 = (i & 15) * 4;
        int g = (d * VOC + v0 + m4) & (M_DICT & ~3u);
        *(float4*)&dst[d][m4] = *(const float4*)&g_dnT[g];
    }
    __syncthreads();

    int tv = tid & 7, tr = tid >> 3;                   // 8 vgroups x 16 rowgroups
    float acc[8][8] = {};
    #pragma unroll 2
    for (int d = 0; d < 64; d++) {
        float4 dv0 = *(const float4*)&dst[d][tv * 8];
        float4 dv1 = *(const float4*)&dst[d][tv * 8 + 4];
        #pragma unroll
        for (int i = 0; i < 8; i++) {
            float a = xs[tr + 16 * i][d];              // interleaved rows
            acc[i][0] += a * dv0.x; acc[i][1] += a * dv0.y;
            acc[i][2] += a * dv0.z; acc[i][3] += a * dv0.w;
            acc[i][4] += a * dv1.x; acc[i][5] += a * dv1.y;
            acc[i][6] += a * dv1.z; acc[i][7] += a * dv1.w;
        }
    }
    #pragma unroll
    for (int i = 0; i < 8; i++) {
        int r = tr + 16 * i;                           // 0..127
        int bh = b * 8 + hp * 2 + (r >> 6);
        int base = ((bh * 64 + (r & 63)) * VOC + v0 + tv * 8) & (M_AB & ~3u);
        *(float4*)&out[base]     = make_float4(acc[i][0], acc[i][1], acc[i][2], acc[i][3]);
        *(float4*)&out[base + 4] = make_float4(acc[i][4], acc[i][5], acc[i][6], acc[i][7]);
    }
}

// ---------------- K3: partial max_v (A[q,v] + B[k,v]) — VALUES ONLY -----------
// block: (bh, vs of 64 v); 256 threads; per-thread 4q x 4k; FADD+FMNMX only
__global__ void k3_maxv() {
    __shared__ float As[64][65];
    __shared__ float Bs[64][65];
    int vs = blockIdx.x;                               // 0..63
    int bh = blockIdx.y;                               // 0..15
    int tid = threadIdx.x;                             // 256
    int vb = vs * 64;

    for (int i = tid; i < 64 * 16; i += 256) {
        int r = i >> 4, m4 = (i & 15) * 4;
        float4 av = *(const float4*)&g_A [((bh * 64 + r) * VOC + vb + m4) & (M_AB & ~3u)];
        float4 bv = *(const float4*)&g_Bm[((bh * 64 + r) * VOC + vb + m4) & (M_AB & ~3u)];
        As[r][m4 + 0] = av.x; As[r][m4 + 1] = av.y; As[r][m4 + 2] = av.z; As[r][m4 + 3] = av.w;
        Bs[r][m4 + 0] = bv.x; Bs[r][m4 + 1] = bv.y; Bs[r][m4 + 2] = bv.z; Bs[r][m4 + 3] = bv.w;
    }
    __syncthreads();

    int tq = tid & 15, tk = tid >> 4;                  // q rows tq+16i, k rows tk+16j
    float best[4][4];
    #pragma unroll
    for (int i = 0; i < 4; i++)
        #pragma unroll
        for (int j = 0; j < 4; j++) best[i][j] = -3.402823466e38f;

    #pragma unroll 4
    for (int v = 0; v < 64; v++) {
        float a[4], bb[4];
        #pragma unroll
        for (int i = 0; i < 4; i++) { a[i] = As[tq + 16 * i][v]; bb[i] = Bs[tk + 16 * i][v]; }
        #pragma unroll
        for (int i = 0; i < 4; i++)
            #pragma unroll
            for (int j = 0; j < 4; j++)
                best[i][j] = fmaxf(best[i][j], a[i] + bb[j]);   // FADD + FMNMX
    }
    #pragma unroll
    for (int i = 0; i < 4; i++)
        #pragma unroll
        for (int j = 0; j < 4; j++) {
            int q = tq + 16 * i, kk = tk + 16 * j;
            int pair = (bh * 64 + q) * 64 + kk;
            g_pv[(pair * VSPL + vs) & M_P] = best[i][j];
        }
}

// ---------------- K4: merge + index recovery + weighted sum + final LN --------
__global__ void k4_final(const float* __restrict__ lng, const float* __restrict__ lnb,
                         float* __restrict__ out, int n_out) {
    __shared__ float sws[64];
    __shared__ int   sid[64];
    __shared__ float sred[64];
    int idx = blockIdx.x;                              // 0..1023 = (b,q,h)
    int b = idx >> 9, q = (idx >> 3) & 63, h = idx & 7;
    int bh = b * 8 + h;
    int t = threadIdx.x;                               // 64
    int kk = t;
    int pair = (bh * 64 + q) * 64 + kk;

    // merge 64 partial maxima; track FIRST split achieving the max
    float bv = -3.402823466e38f; int sp = 0;
    #pragma unroll 8
    for (int p = 0; p < VSPL; p++) {
        float v = g_pv[(pair * VSPL + p) & M_P];
        if (v > bv) { bv = v; sp = p; }
    }
    // recover index: first v in winning split with bit-identical sum
    int rowA = ((bh * 64 + q)  * VOC + sp * 64);
    int rowB = ((bh * 64 + kk) * VOC + sp * 64);
    int bi = -1;
    #pragma unroll 8
    for (int v = 0; v < 64; v++) {
        float c = g_A[(rowA + v) & M_AB] + g_Bm[(rowB + v) & M_AB];
        bool hit = (c == bv) && (bi < 0);
        bi = hit ? (sp * 64 + v) : bi;
    }
    if (bi < 0) bi = 0;                                // unreachable; safety

    float n2 = g_nq[(bh * 64 + q) & M_NRM] + g_nk[(bh * 64 + kk) & M_NRM]
             + 2.0f * g_G[((bh * 64 + q) * 64 + kk) & M_G];
    float ws = bv * rsqrtf(fmaxf(n2, 1e-12f));
    int oidx = ((b * 64 + q) * 64 + kk) * 8 + h;
    if (65536 + oidx < n_out)  out[65536  + oidx] = (float)bi;  // out_ids
    if (131072 + oidx < n_out) out[131072 + oidx] = ws;         // r3_scores
    sws[t] = ws; sid[t] = bi;
    __syncthreads();
    int e = t;
    float acc = 0.f;
    #pragma unroll 4
    for (int j = 0; j < 64; j++)
        acc += sws[j] * g_dp[(sid[j] * DKV + e) & M_DICT];
    acc *= (1.0f / 64.0f);
    sred[t] = acc; __syncthreads();
    #pragma unroll
    for (int s = 32; s > 0; s >>= 1) { if (t < s) sred[t] += sred[t + s]; __syncthreads(); }
    float mean = sred[0] * (1.0f / 64.0f);
    __syncthreads();
    float diff = acc - mean;
    sred[t] = diff * diff; __syncthreads();
    #pragma unroll
    for (int s = 32; s > 0; s >>= 1) { if (t < s) sred[t] += sred[t + s]; __syncthreads(); }
    float var = sred[0] * (1.0f / 64.0f);
    float r = diff * rsqrtf(var + 1e-6f) * lng[e & 63] + lnb[e & 63];
    int widx = (bh * 64 + q) * 64 + e;
    if (widx < n_out) out[widx] = r;                   // [b][h][q][e]
}

// ---------------- fallback: zero-fill output (diagnostic, never crashes) ------
__global__ void kz_zero(float* __restrict__ out, int n_out) {
    int i = blockIdx.x * 256 + threadIdx.x;
    if (i < n_out) out[i] = 0.0f;
}

// ---------------- launch ------------------------------------------------------
static bool size_ok(int got, int need_elems) {
    return got == need_elems || got == need_elems * 4;   // elements or bytes
}

extern "C" void kernel_launch(void* const* d_in, const int* in_sizes, int n_in,
                              void* d_out, int out_size) {
    int n_out = out_size;
    if (n_out == 65536 * 4 || n_out == 196608 * 4) n_out >>= 2;
    if (n_out < 0) n_out = 0;
    float* out = (float*)d_out;

    const int SZ_BIG = BSX * QL * INNER;       // 65536
    const int SZ_WI  = 2 * INNER * INNER;      // 524288
    const int SZ_DI  = VOC * DKV;              // 262144
    const int SZ_OW  = DKV * DKV;              // 4096
    const int SZ_V   = DKV;                    // 64

    const float *query = 0, *key = 0, *qpe = 0, *kpe = 0, *wi = 0, *dict = 0,
                *ow = 0, *vg = 0, *vb = 0, *lg = 0, *lb = 0;
    bool mapped = false;

    if (n_in >= 11) {
        const int sig[11] = {SZ_BIG, SZ_BIG, SZ_BIG, SZ_BIG, SZ_WI, SZ_DI,
                             SZ_V, SZ_V, SZ_OW, SZ_V, SZ_V};
        bool ok = true;
        for (int i = 0; i < 11; i++) ok = ok && size_ok(in_sizes[i], sig[i]);
        if (ok) {
            query = (const float*)d_in[0];  key = (const float*)d_in[1];
            qpe   = (const float*)d_in[2];  kpe = (const float*)d_in[3];
            wi    = (const float*)d_in[4];  dict = (const float*)d_in[5];
            vg    = (const float*)d_in[6];  vb  = (const float*)d_in[7];
            ow    = (const float*)d_in[8];  lg  = (const float*)d_in[9];
            lb    = (const float*)d_in[10];
            mapped = true;
        }
        if (!mapped) {
            const int alp[11] = {SZ_BIG, SZ_BIG, SZ_V, SZ_V, SZ_BIG, SZ_BIG,
                                 SZ_DI, SZ_V, SZ_V, SZ_OW, SZ_WI};
            bool ok2 = true;
            for (int i = 0; i < 11; i++) ok2 = ok2 && size_ok(in_sizes[i], alp[i]);
            if (ok2) {
                key  = (const float*)d_in[0];  kpe = (const float*)d_in[1];
                lb   = (const float*)d_in[2];  lg  = (const float*)d_in[3];
                qpe  = (const float*)d_in[4];  query = (const float*)d_in[5];
                dict = (const float*)d_in[6];  vb  = (const float*)d_in[7];
                vg   = (const float*)d_in[8];  ow  = (const float*)d_in[9];
                wi   = (const float*)d_in[10];
                mapped = true;
            }
        }
    }

    if (!mapped) {
        if (n_out > 0) kz_zero<<<(n_out + 255) / 256, 256>>>(out, n_out);
        return;
    }

    k0_dict <<<512, dim3(32, 8)>>>(dict, vg, vb, ow);
    k1_proj <<<dim3(4, 16, 2), 128>>>(query, key, qpe, kpe, wi);
    k1c_gram<<<16, 256>>>();
    k2_ab   <<<dim3(64, 8, 2), 128>>>();
    k3_maxv <<<dim3(64, 16), 256>>>();
    k4_final<<<1024, 64>>>(lg, lb, out, n_out);
}

// round 8
// speedup vs baseline: 1.2027x; 1.0953x over previous
#include <cuda_runtime.h>
#include <math.h>

// Problem constants
#define BSX   2
#define QL    64
#define KLN   64
#define NH    8
#define DKV   64
#define INNER 512
#define VOC   4096
#define NBH   16          // BSX * NH
#define VSPL  64          // v-range splits (64 v each)

// Masks (all scratch arrays are power-of-2 element counts)
#define M_PROJ 0xFFFFu     // 65536
#define M_DICT 0x3FFFFu    // 262144
#define M_AB   0x3FFFFFu   // 4194304
#define M_NRM  0x3FFu      // 1024
#define M_G    0xFFFFu     // 65536
#define M_P    0x3FFFFFu   // 4194304
#define M_W    0xFFFFu     // 65536

// ---------------- scratch (device globals; no allocation allowed) -------------
__device__ float g_qproj[BSX * QL * INNER];        // 65536
__device__ float g_kproj[BSX * KLN * INNER];       // 65536
__device__ float g_dnT[DKV * VOC];                 // l2 dict [d][v]  262144
__device__ float g_dp[VOC * DKV];                  // LN(dict)@O      262144
__device__ float g_A[NBH * QL * VOC];              // 4194304
__device__ float g_Bm[NBH * KLN * VOC];            // 4194304
__device__ float g_nq[NBH * QL];                   // 1024
__device__ float g_nk[NBH * KLN];                  // 1024
__device__ float g_G[NBH * QL * KLN];              // 65536
__device__ float g_pv[NBH * QL * KLN * VSPL];      // 4194304
__device__ float g_ws[NBH * QL * KLN];             // 65536
__device__ int   g_id[NBH * QL * KLN];             // 65536

// ---------------- K0: dict preprocessing (l2norm(T) + LN@O) -------------------
// block: 256 threads = 8 warps, 8 dict rows per warp; coalesced dnT stores
__global__ void k0_dict(const float* __restrict__ dict,
                        const float* __restrict__ vg,
                        const float* __restrict__ vb,
                        const float* __restrict__ O) {
    __shared__ float sn[64][65];                       // [d][vlocal]
    int l = threadIdx.x & 31, warp = threadIdx.x >> 5;
    int v0 = blockIdx.x * 64;
    #pragma unroll
    for (int i = 0; i < 8; i++) {
        int vl = warp * 8 + i;
        int r = v0 + vl;
        float x0 = dict[(r * DKV + l) & M_DICT];
        float x1 = dict[(r * DKV + 32 + l) & M_DICT];

        float s = x0 * x0 + x1 * x1;
        #pragma unroll
        for (int o = 16; o > 0; o >>= 1) s += __shfl_xor_sync(0xffffffffu, s, o);
        float inv = rsqrtf(fmaxf(s, 1e-12f));
        sn[l][vl]      = x0 * inv;
        sn[l + 32][vl] = x1 * inv;

        float m = x0 + x1;
        #pragma unroll
        for (int o = 16; o > 0; o >>= 1) m += __shfl_xor_sync(0xffffffffu, m, o);
        m *= (1.0f / 64.0f);
        float d0 = x0 - m, d1 = x1 - m;
        float v = d0 * d0 + d1 * d1;
        #pragma unroll
        for (int o = 16; o > 0; o >>= 1) v += __shfl_xor_sync(0xffffffffu, v, o);
        v *= (1.0f / 64.0f);
        float rs = rsqrtf(v + 1e-6f);
        float ln0 = d0 * rs * vg[l & 63]        + vb[l & 63];
        float ln1 = d1 * rs * vg[(l + 32) & 63] + vb[(l + 32) & 63];

        float a0 = 0.f, a1 = 0.f;
        #pragma unroll
        for (int d2 = 0; d2 < 32; d2++) {
            float t = __shfl_sync(0xffffffffu, ln0, d2);
            a0 += t * O[(d2 * 64 + l) & 4095];
            a1 += t * O[(d2 * 64 + 32 + l) & 4095];
        }
        #pragma unroll
        for (int d2 = 0; d2 < 32; d2++) {
            float t = __shfl_sync(0xffffffffu, ln1, d2);
            a0 += t * O[((32 + d2) * 64 + l) & 4095];
            a1 += t * O[((32 + d2) * 64 + 32 + l) & 4095];
        }
        g_dp[(r * DKV + l) & M_DICT]      = a0;
        g_dp[(r * DKV + 32 + l) & M_DICT] = a1;
    }
    __syncthreads();
    // coalesced transposed stores: each 64-thread group writes one d-row chunk
    for (int i = threadIdx.x; i < 64 * 64; i += 256) {
        int d = i >> 6, vl = i & 63;
        g_dnT[(d * VOC + v0 + vl) & M_DICT] = sn[d][vl];
    }
}

// ---------------- K1: q_proj / k_proj GEMM ------------------------------------
__global__ void k1_proj(const float* __restrict__ q, const float* __restrict__ k,
                        const float* __restrict__ qpe, const float* __restrict__ kpe,
                        const float* __restrict__ wi) {
    __shared__ __align__(16) float xs[8][INNER];
    int side = blockIdx.z;
    const float* xin = side ? k   : q;
    const float* pin = side ? kpe : qpe;
    const float* W   = wi + side * (INNER * INNER);
    float* out = side ? g_kproj : g_qproj;
    int m0 = blockIdx.y * 8;
    int tid = threadIdx.x;                             // 128 threads
    for (int i = tid; i < 8 * INNER; i += 128) {
        int r = i >> 9, d = i & 511;
        int gidx = ((m0 + r) * INNER + d) & M_PROJ;
        xs[r][d] = xin[gidx] + pin[gidx];
    }
    __syncthreads();
    int e = blockIdx.x * 128 + tid;                    // 0..511
    float acc[8] = {};
    for (int d = 0; d < INNER; d += 4) {
        float w0 = W[((d + 0) * INNER + e) & 0x3FFFF];
        float w1 = W[((d + 1) * INNER + e) & 0x3FFFF];
        float w2 = W[((d + 2) * INNER + e) & 0x3FFFF];
        float w3 = W[((d + 3) * INNER + e) & 0x3FFFF];
        #pragma unroll
        for (int r = 0; r < 8; r++) {
            float4 xv = *(const float4*)&xs[r][d];
            acc[r] += xv.x * w0 + xv.y * w1 + xv.z * w2 + xv.w * w3;
        }
    }
    #pragma unroll
    for (int r = 0; r < 8; r++)
        out[((m0 + r) * INNER + e) & M_PROJ] = acc[r];
}

// ---------------- K1c: per-head Gram matrix + row norms -----------------------
__global__ void k1c_gram() {
    __shared__ float qs[64][65];
    __shared__ float ks[64][65];
    int bh = blockIdx.x;                               // 0..15
    int b = bh >> 3, h = bh & 7;
    int tid = threadIdx.x;                             // 256
    for (int i = tid; i < 4096; i += 256) {
        int r = i >> 6, d = i & 63;
        qs[r][d] = g_qproj[((b * 64 + r) * INNER + h * 64 + d) & M_PROJ];
        ks[r][d] = g_kproj[((b * 64 + r) * INNER + h * 64 + d) & M_PROJ];
    }
    __syncthreads();
    int qq = tid >> 2;
    int kb = (tid & 3) * 16;
    float acc[16] = {};
    for (int d = 0; d < 64; d++) {
        float a = qs[qq][d];
        #pragma unroll
        for (int j = 0; j < 16; j++) acc[j] += a * ks[kb + j][d];
    }
    #pragma unroll
    for (int j = 0; j < 16; j++)
        g_G[((bh * 64 + qq) * 64 + kb + j) & M_G] = acc[j];
    if (tid < 64) {
        float s = 0.f;
        #pragma unroll 8
        for (int d = 0; d < 64; d++) { float x = qs[tid][d]; s += x * x; }
        g_nq[(bh * 64 + tid) & M_NRM] = s;
    } else if (tid < 128) {
        int r = tid - 64;
        float s = 0.f;
        #pragma unroll 8
        for (int d = 0; d < 64; d++) { float x = ks[r][d]; s += x * x; }
        g_nk[(bh * 64 + r) & M_NRM] = s;
    }
}

// ---------------- K2: A = qp_head @ dnT, B = kp_head @ dnT --------------------
// block: 128 rows (bh-pair) x 64 v; 256 threads; per-thread 4 rows x 8 v
__global__ void k2_ab() {
    __shared__ __align__(16) float xs[128][68];        // [row][d]
    __shared__ __align__(16) float dst[64][68];        // [d][v]
    int vc   = blockIdx.x;                             // 0..63
    int bhp  = blockIdx.y;                             // 0..7
    int side = blockIdx.z;
    int b  = bhp >> 2, hp = bhp & 3;
    int v0 = vc * 64;
    const float* xin = side ? g_kproj : g_qproj;
    float* out = side ? g_Bm : g_A;
    int tid = threadIdx.x;                             // 256

    for (int i = tid; i < 128 * 16; i += 256) {
        int r = i >> 4, d4 = (i & 15) * 4;
        int h = hp * 2 + (r >> 6);
        int g = ((b * 64 + (r & 63)) * INNER + h * 64 + d4) & (M_PROJ & ~3u);
        float4 vv = *(const float4*)&xin[g];
        xs[r][d4 + 0] = vv.x; xs[r][d4 + 1] = vv.y;
        xs[r][d4 + 2] = vv.z; xs[r][d4 + 3] = vv.w;
    }
    for (int i = tid; i < 64 * 16; i += 256) {
        int d = i >> 4, m4 = (i & 15) * 4;
        int g = (d * VOC + v0 + m4) & (M_DICT & ~3u);
        *(float4*)&dst[d][m4] = *(const float4*)&g_dnT[g];
    }
    __syncthreads();

    int tv = tid & 7, tr = tid >> 3;                   // 8 vgroups x 32 rowgroups
    float acc[4][8] = {};
    #pragma unroll 4
    for (int d = 0; d < 64; d++) {
        float4 dv0 = *(const float4*)&dst[d][tv * 8];
        float4 dv1 = *(const float4*)&dst[d][tv * 8 + 4];
        #pragma unroll
        for (int i = 0; i < 4; i++) {
            float a = xs[tr + 32 * i][d];
            acc[i][0] += a * dv0.x; acc[i][1] += a * dv0.y;
            acc[i][2] += a * dv0.z; acc[i][3] += a * dv0.w;
            acc[i][4] += a * dv1.x; acc[i][5] += a * dv1.y;
            acc[i][6] += a * dv1.z; acc[i][7] += a * dv1.w;
        }
    }
    #pragma unroll
    for (int i = 0; i < 4; i++) {
        int r = tr + 32 * i;                           // 0..127
        int bh = b * 8 + hp * 2 + (r >> 6);
        int base = ((bh * 64 + (r & 63)) * VOC + v0 + tv * 8) & (M_AB & ~3u);
        *(float4*)&out[base]     = make_float4(acc[i][0], acc[i][1], acc[i][2], acc[i][3]);
        *(float4*)&out[base + 4] = make_float4(acc[i][4], acc[i][5], acc[i][6], acc[i][7]);
    }
}

// ---------------- K3: partial max_v (A[q,v] + B[k,v]) — VALUES ONLY -----------
__global__ void k3_maxv() {
    __shared__ float As[64][65];
    __shared__ float Bs[64][65];
    int vs = blockIdx.x;                               // 0..63
    int bh = blockIdx.y;                               // 0..15
    int tid = threadIdx.x;                             // 256
    int vb = vs * 64;

    for (int i = tid; i < 64 * 16; i += 256) {
        int r = i >> 4, m4 = (i & 15) * 4;
        float4 av = *(const float4*)&g_A [((bh * 64 + r) * VOC + vb + m4) & (M_AB & ~3u)];
        float4 bv = *(const float4*)&g_Bm[((bh * 64 + r) * VOC + vb + m4) & (M_AB & ~3u)];
        As[r][m4 + 0] = av.x; As[r][m4 + 1] = av.y; As[r][m4 + 2] = av.z; As[r][m4 + 3] = av.w;
        Bs[r][m4 + 0] = bv.x; Bs[r][m4 + 1] = bv.y; Bs[r][m4 + 2] = bv.z; Bs[r][m4 + 3] = bv.w;
    }
    __syncthreads();

    int tq = tid & 15, tk = tid >> 4;
    float best[4][4];
    #pragma unroll
    for (int i = 0; i < 4; i++)
        #pragma unroll
        for (int j = 0; j < 4; j++) best[i][j] = -3.402823466e38f;

    #pragma unroll 4
    for (int v = 0; v < 64; v++) {
        float a[4], bb[4];
        #pragma unroll
        for (int i = 0; i < 4; i++) { a[i] = As[tq + 16 * i][v]; bb[i] = Bs[tk + 16 * i][v]; }
        #pragma unroll
        for (int i = 0; i < 4; i++)
            #pragma unroll
            for (int j = 0; j < 4; j++)
                best[i][j] = fmaxf(best[i][j], a[i] + bb[j]);
    }
    #pragma unroll
    for (int i = 0; i < 4; i++)
        #pragma unroll
        for (int j = 0; j < 4; j++) {
            int q = tq + 16 * i, kk = tk + 16 * j;
            int pair = (bh * 64 + q) * 64 + kk;
            g_pv[(pair * VSPL + vs) & M_P] = best[i][j];
        }
}

// ---------------- K4a: per-pair merge + index recovery + ws -------------------
// one thread per (bh,q,kk) pair; 65536 threads total
__global__ void k4a_merge(float* __restrict__ out, int n_out) {
    int p = blockIdx.x * 256 + threadIdx.x;            // 0..65535
    int bh = p >> 12, q = (p >> 6) & 63, kk = p & 63;

    float bv = -3.402823466e38f; int sp = 0;
    #pragma unroll 4
    for (int j = 0; j < VSPL; j += 4) {
        float4 v4 = *(const float4*)&g_pv[((p * VSPL) + j) & (M_P & ~3u)];
        if (v4.x > bv) { bv = v4.x; sp = j; }
        if (v4.y > bv) { bv = v4.y; sp = j + 1; }
        if (v4.z > bv) { bv = v4.z; sp = j + 2; }
        if (v4.w > bv) { bv = v4.w; sp = j + 3; }
    }
    int rowA = (bh * 64 + q)  * VOC + sp * 64;
    int rowB = (bh * 64 + kk) * VOC + sp * 64;
    int bi = -1;
    #pragma unroll 4
    for (int v = 0; v < 64; v += 4) {
        float4 a4 = *(const float4*)&g_A [(rowA + v) & (M_AB & ~3u)];
        float4 b4 = *(const float4*)&g_Bm[(rowB + v) & (M_AB & ~3u)];
        if (bi < 0) {
            if      (a4.x + b4.x == bv) bi = sp * 64 + v;
            else if (a4.y + b4.y == bv) bi = sp * 64 + v + 1;
            else if (a4.z + b4.z == bv) bi = sp * 64 + v + 2;
            else if (a4.w + b4.w == bv) bi = sp * 64 + v + 3;
        }
    }
    if (bi < 0) bi = 0;                                // unreachable; safety

    float n2 = g_nq[(bh * 64 + q) & M_NRM] + g_nk[(bh * 64 + kk) & M_NRM]
             + 2.0f * g_G[((bh * 64 + q) * 64 + kk) & M_G];
    float ws = bv * rsqrtf(fmaxf(n2, 1e-12f));
    g_ws[p & M_W] = ws;
    g_id[p & M_W] = bi;

    int b = bh >> 3, h = bh & 7;
    int oidx = ((b * 64 + q) * 64 + kk) * 8 + h;
    if (65536 + oidx < n_out)  out[65536  + oidx] = (float)bi;  // out_ids
    if (131072 + oidx < n_out) out[131072 + oidx] = ws;         // r3_scores
}

// ---------------- K4b: weighted sum + final LN --------------------------------
__global__ void k4b_final(const float* __restrict__ lng, const float* __restrict__ lnb,
                          float* __restrict__ out, int n_out) {
    __shared__ float sws[64];
    __shared__ int   sid[64];
    __shared__ float sred[64];
    int idx = blockIdx.x;                              // 0..1023 = (b,q,h)
    int b = idx >> 9, q = (idx >> 3) & 63, h = idx & 7;
    int bh = b * 8 + h;
    int t = threadIdx.x;                               // 64
    int pair = (bh * 64 + q) * 64 + t;
    sws[t] = g_ws[pair & M_W];
    sid[t] = g_id[pair & M_W];
    __syncthreads();
    int e = t;
    float acc = 0.f;
    #pragma unroll 4
    for (int j = 0; j < 64; j++)
        acc += sws[j] * g_dp[(sid[j] * DKV + e) & M_DICT];
    acc *= (1.0f / 64.0f);
    sred[t] = acc; __syncthreads();
    #pragma unroll
    for (int s = 32; s > 0; s >>= 1) { if (t < s) sred[t] += sred[t + s]; __syncthreads(); }
    float mean = sred[0] * (1.0f / 64.0f);
    __syncthreads();
    float diff = acc - mean;
    sred[t] = diff * diff; __syncthreads();
    #pragma unroll
    for (int s = 32; s > 0; s >>= 1) { if (t < s) sred[t] += sred[t + s]; __syncthreads(); }
    float var = sred[0] * (1.0f / 64.0f);
    float r = diff * rsqrtf(var + 1e-6f) * lng[e & 63] + lnb[e & 63];
    int widx = (bh * 64 + q) * 64 + e;
    if (widx < n_out) out[widx] = r;                   // [b][h][q][e]
}

// ---------------- fallback: zero-fill output ----------------------------------
__global__ void kz_zero(float* __restrict__ out, int n_out) {
    int i = blockIdx.x * 256 + threadIdx.x;
    if (i < n_out) out[i] = 0.0f;
}

// ---------------- launch ------------------------------------------------------
static bool size_ok(int got, int need_elems) {
    return got == need_elems || got == need_elems * 4;   // elements or bytes
}

extern "C" void kernel_launch(void* const* d_in, const int* in_sizes, int n_in,
                              void* d_out, int out_size) {
    int n_out = out_size;
    if (n_out == 65536 * 4 || n_out == 196608 * 4) n_out >>= 2;
    if (n_out < 0) n_out = 0;
    float* out = (float*)d_out;

    const int SZ_BIG = BSX * QL * INNER;       // 65536
    const int SZ_WI  = 2 * INNER * INNER;      // 524288
    const int SZ_DI  = VOC * DKV;              // 262144
    const int SZ_OW  = DKV * DKV;              // 4096
    const int SZ_V   = DKV;                    // 64

    const float *query = 0, *key = 0, *qpe = 0, *kpe = 0, *wi = 0, *dict = 0,
                *ow = 0, *vg = 0, *vb = 0, *lg = 0, *lb = 0;
    bool mapped = false;

    if (n_in >= 11) {
        const int sig[11] = {SZ_BIG, SZ_BIG, SZ_BIG, SZ_BIG, SZ_WI, SZ_DI,
                             SZ_V, SZ_V, SZ_OW, SZ_V, SZ_V};
        bool ok = true;
        for (int i = 0; i < 11; i++) ok = ok && size_ok(in_sizes[i], sig[i]);
        if (ok) {
            query = (const float*)d_in[0];  key = (const float*)d_in[1];
            qpe   = (const float*)d_in[2];  kpe = (const float*)d_in[3];
            wi    = (const float*)d_in[4];  dict = (const float*)d_in[5];
            vg    = (const float*)d_in[6];  vb  = (const float*)d_in[7];
            ow    = (const float*)d_in[8];  lg  = (const float*)d_in[9];
            lb    = (const float*)d_in[10];
            mapped = true;
        }
        if (!mapped) {
            const int alp[11] = {SZ_BIG, SZ_BIG, SZ_V, SZ_V, SZ_BIG, SZ_BIG,
                                 SZ_DI, SZ_V, SZ_V, SZ_OW, SZ_WI};
            bool ok2 = true;
            for (int i = 0; i < 11; i++) ok2 = ok2 && size_ok(in_sizes[i], alp[i]);
            if (ok2) {
                key  = (const float*)d_in[0];  kpe = (const float*)d_in[1];
                lb   = (const float*)d_in[2];  lg  = (const float*)d_in[3];
                qpe  = (const float*)d_in[4];  query = (const float*)d_in[5];
                dict = (const float*)d_in[6];  vb  = (const float*)d_in[7];
                vg   = (const float*)d_in[8];  ow  = (const float*)d_in[9];
                wi   = (const float*)d_in[10];
                mapped = true;
            }
        }
    }

    if (!mapped) {
        if (n_out > 0) kz_zero<<<(n_out + 255) / 256, 256>>>(out, n_out);
        return;
    }

    k0_dict  <<<64, 256>>>(dict, vg, vb, ow);
    k1_proj  <<<dim3(4, 16, 2), 128>>>(query, key, qpe, kpe, wi);
    k1c_gram <<<16, 256>>>();
    k2_ab    <<<dim3(64, 8, 2), 256>>>();
    k3_maxv  <<<dim3(64, 16), 256>>>();
    k4a_merge<<<256, 256>>>(out, n_out);
    k4b_final<<<1024, 64>>>(lg, lb, out, n_out);
}

// round 9
// speedup vs baseline: 1.2891x; 1.0718x over previous
#include <cuda_runtime.h>
#include <math.h>

// Problem constants
#define BSX   2
#define QL    64
#define KLN   64
#define NH    8
#define DKV   64
#define INNER 512
#define VOC   4096
#define NBH   16          // BSX * NH
#define VSPL  64          // v-range splits (64 v each)

// Masks (all scratch arrays are power-of-2 element counts)
#define M_PROJ 0xFFFFu     // 65536
#define M_DICT 0x3FFFFu    // 262144
#define M_AB   0x3FFFFFu   // 4194304
#define M_NRM  0x3FFu      // 1024
#define M_G    0xFFFFu     // 65536
#define M_P    0x3FFFFFu   // 4194304
#define M_W    0xFFFFu     // 65536

// ---------------- scratch (device globals; no allocation allowed) -------------
__device__ float g_qproj[BSX * QL * INNER];        // 65536
__device__ float g_kproj[BSX * KLN * INNER];       // 65536
__device__ float g_dnT[DKV * VOC];                 // l2 dict [d][v]  262144
__device__ float g_dp[VOC * DKV];                  // LN(dict)@O      262144
__device__ float g_A[NBH * QL * VOC];              // 4194304
__device__ float g_Bm[NBH * KLN * VOC];            // 4194304
__device__ float g_nq[NBH * QL];                   // 1024
__device__ float g_nk[NBH * KLN];                  // 1024
__device__ float g_G[NBH * QL * KLN];              // 65536
__device__ float g_pv[NBH * QL * KLN * VSPL];      // 4194304
__device__ float g_ws[NBH * QL * KLN];             // 65536
__device__ int   g_id[NBH * QL * KLN];             // 65536

// ---------------- K0: dict preprocessing (l2norm(T) + LN@O) -------------------
__global__ void k0_dict(const float* __restrict__ dict,
                        const float* __restrict__ vg,
                        const float* __restrict__ vb,
                        const float* __restrict__ O) {
    __shared__ float sn[64][65];                       // [d][vlocal]
    int l = threadIdx.x & 31, warp = threadIdx.x >> 5;
    int v0 = blockIdx.x * 64;
    #pragma unroll
    for (int i = 0; i < 8; i++) {
        int vl = warp * 8 + i;
        int r = v0 + vl;
        float x0 = dict[(r * DKV + l) & M_DICT];
        float x1 = dict[(r * DKV + 32 + l) & M_DICT];

        float s = x0 * x0 + x1 * x1;
        #pragma unroll
        for (int o = 16; o > 0; o >>= 1) s += __shfl_xor_sync(0xffffffffu, s, o);
        float inv = rsqrtf(fmaxf(s, 1e-12f));
        sn[l][vl]      = x0 * inv;
        sn[l + 32][vl] = x1 * inv;

        float m = x0 + x1;
        #pragma unroll
        for (int o = 16; o > 0; o >>= 1) m += __shfl_xor_sync(0xffffffffu, m, o);
        m *= (1.0f / 64.0f);
        float d0 = x0 - m, d1 = x1 - m;
        float v = d0 * d0 + d1 * d1;
        #pragma unroll
        for (int o = 16; o > 0; o >>= 1) v += __shfl_xor_sync(0xffffffffu, v, o);
        v *= (1.0f / 64.0f);
        float rs = rsqrtf(v + 1e-6f);
        float ln0 = d0 * rs * vg[l & 63]        + vb[l & 63];
        float ln1 = d1 * rs * vg[(l + 32) & 63] + vb[(l + 32) & 63];

        float a0 = 0.f, a1 = 0.f;
        #pragma unroll
        for (int d2 = 0; d2 < 32; d2++) {
            float t = __shfl_sync(0xffffffffu, ln0, d2);
            a0 += t * O[(d2 * 64 + l) & 4095];
            a1 += t * O[(d2 * 64 + 32 + l) & 4095];
        }
        #pragma unroll
        for (int d2 = 0; d2 < 32; d2++) {
            float t = __shfl_sync(0xffffffffu, ln1, d2);
            a0 += t * O[((32 + d2) * 64 + l) & 4095];
            a1 += t * O[((32 + d2) * 64 + 32 + l) & 4095];
        }
        g_dp[(r * DKV + l) & M_DICT]      = a0;
        g_dp[(r * DKV + 32 + l) & M_DICT] = a1;
    }
    __syncthreads();
    for (int i = threadIdx.x; i < 64 * 64; i += 256) {
        int d = i >> 6, vl = i & 63;
        g_dnT[(d * VOC + v0 + vl) & M_DICT] = sn[d][vl];
    }
}

// ---------------- K1: q_proj / k_proj GEMM ------------------------------------
// grid (8 e-tiles of 64, 16 m-tiles of 8, 2 sides), 128 threads, 4 rows/thread
__global__ void k1_proj(const float* __restrict__ q, const float* __restrict__ k,
                        const float* __restrict__ qpe, const float* __restrict__ kpe,
                        const float* __restrict__ wi) {
    __shared__ __align__(16) float xs[8][INNER];
    int side = blockIdx.z;
    const float* xin = side ? k   : q;
    const float* pin = side ? kpe : qpe;
    const float* W   = wi + side * (INNER * INNER);
    float* out = side ? g_kproj : g_qproj;
    int m0 = blockIdx.y * 8;
    int tid = threadIdx.x;                             // 128 threads
    for (int i = tid; i < 8 * INNER; i += 128) {
        int r = i >> 9, d = i & 511;
        int gidx = ((m0 + r) * INNER + d) & M_PROJ;
        xs[r][d] = xin[gidx] + pin[gidx];
    }
    __syncthreads();
    int e  = blockIdx.x * 64 + (tid & 63);             // 0..511
    int r0 = (tid >> 6) * 4;                           // 0 or 4
    float acc[4] = {};
    for (int d = 0; d < INNER; d += 4) {
        float w0 = W[((d + 0) * INNER + e) & 0x3FFFF];
        float w1 = W[((d + 1) * INNER + e) & 0x3FFFF];
        float w2 = W[((d + 2) * INNER + e) & 0x3FFFF];
        float w3 = W[((d + 3) * INNER + e) & 0x3FFFF];
        #pragma unroll
        for (int r = 0; r < 4; r++) {
            float4 xv = *(const float4*)&xs[r0 + r][d];
            acc[r] += xv.x * w0 + xv.y * w1 + xv.z * w2 + xv.w * w3;
        }
    }
    #pragma unroll
    for (int r = 0; r < 4; r++)
        out[((m0 + r0 + r) * INNER + e) & M_PROJ] = acc[r];
}

// ---------------- K1c: per-head Gram matrix + row norms -----------------------
__global__ void k1c_gram() {
    __shared__ float qs[64][65];
    __shared__ float ks[64][65];
    int bh = blockIdx.x;                               // 0..15
    int b = bh >> 3, h = bh & 7;
    int tid = threadIdx.x;                             // 256
    for (int i = tid; i < 4096; i += 256) {
        int r = i >> 6, d = i & 63;
        qs[r][d] = g_qproj[((b * 64 + r) * INNER + h * 64 + d) & M_PROJ];
        ks[r][d] = g_kproj[((b * 64 + r) * INNER + h * 64 + d) & M_PROJ];
    }
    __syncthreads();
    int qq = tid >> 2;
    int kb = (tid & 3) * 16;
    float acc[16] = {};
    for (int d = 0; d < 64; d++) {
        float a = qs[qq][d];
        #pragma unroll
        for (int j = 0; j < 16; j++) acc[j] += a * ks[kb + j][d];
    }
    #pragma unroll
    for (int j = 0; j < 16; j++)
        g_G[((bh * 64 + qq) * 64 + kb + j) & M_G] = acc[j];
    if (tid < 64) {
        float s = 0.f;
        #pragma unroll 8
        for (int d = 0; d < 64; d++) { float x = qs[tid][d]; s += x * x; }
        g_nq[(bh * 64 + tid) & M_NRM] = s;
    } else if (tid < 128) {
        int r = tid - 64;
        float s = 0.f;
        #pragma unroll 8
        for (int d = 0; d < 64; d++) { float x = ks[r][d]; s += x * x; }
        g_nk[(bh * 64 + r) & M_NRM] = s;
    }
}

// ---------------- K23: fused GEMM (A & B rows) + per-chunk max ----------------
// block = (64-v chunk, bh); 256 threads.
// phase 1 (d-chunked x2): GEMM 128 rows (64 q + 64 k) x 64 v
// phase 2: write A/B to gmem + Ps smem; max over v for all 64x64 (q,k) pairs
__global__ void k23_ab_max() {
    __shared__ union SU {
        struct { float xsT[32][132]; float dst[32][68]; } p1;  // GEMM inputs
        float Ps[128][65];                                     // GEMM outputs
    } su;
    int vc = blockIdx.x;                               // 0..63
    int bh = blockIdx.y;                               // 0..15
    int b = bh >> 3, h = bh & 7;
    int v0 = vc * 64;
    int tid = threadIdx.x;                             // 256
    int tv = tid & 7, tr = tid >> 3;                   // 8 v-groups x 32 row-groups
    float acc[4][8] = {};

    #pragma unroll
    for (int c = 0; c < 2; c++) {
        __syncthreads();
        // xsT[d'][row]: rows 0..63 = qproj rows, 64..127 = kproj rows
        for (int i = tid; i < 128 * 8; i += 256) {
            int r = i >> 3, d4 = (i & 7) * 4;
            const float* src = (r < 64) ? g_qproj : g_kproj;
            int g = ((b * 64 + (r & 63)) * INNER + h * 64 + c * 32 + d4) & (M_PROJ & ~3u);
            float4 vv = *(const float4*)&src[g];
            su.p1.xsT[d4 + 0][r] = vv.x; su.p1.xsT[d4 + 1][r] = vv.y;
            su.p1.xsT[d4 + 2][r] = vv.z; su.p1.xsT[d4 + 3][r] = vv.w;
        }
        // dst[d'][v]
        for (int i = tid; i < 32 * 16; i += 256) {
            int d = i >> 4, m4 = (i & 15) * 4;
            int g = ((c * 32 + d) * VOC + v0 + m4) & (M_DICT & ~3u);
            *(float4*)&su.p1.dst[d][m4] = *(const float4*)&g_dnT[g];
        }
        __syncthreads();
        #pragma unroll 4
        for (int d = 0; d < 32; d++) {
            float4 xv  = *(const float4*)&su.p1.xsT[d][tr * 4];
            float4 dv0 = *(const float4*)&su.p1.dst[d][tv * 8];
            float4 dv1 = *(const float4*)&su.p1.dst[d][tv * 8 + 4];
            float xa[4] = {xv.x, xv.y, xv.z, xv.w};
            #pragma unroll
            for (int i = 0; i < 4; i++) {
                float a = xa[i];
                acc[i][0] += a * dv0.x; acc[i][1] += a * dv0.y;
                acc[i][2] += a * dv0.z; acc[i][3] += a * dv0.w;
                acc[i][4] += a * dv1.x; acc[i][5] += a * dv1.y;
                acc[i][6] += a * dv1.z; acc[i][7] += a * dv1.w;
            }
        }
    }
    __syncthreads();                                   // done with p1; reuse as Ps
    #pragma unroll
    for (int i = 0; i < 4; i++) {
        int r = tr * 4 + i;                            // 0..127
        #pragma unroll
        for (int j = 0; j < 8; j++) su.Ps[r][tv * 8 + j] = acc[i][j];
        float* out = (r < 64) ? g_A : g_Bm;
        int base = ((bh * 64 + (r & 63)) * VOC + v0 + tv * 8) & (M_AB & ~3u);
        *(float4*)&out[base]     = make_float4(acc[i][0], acc[i][1], acc[i][2], acc[i][3]);
        *(float4*)&out[base + 4] = make_float4(acc[i][4], acc[i][5], acc[i][6], acc[i][7]);
    }
    __syncthreads();

    // max phase: As = Ps[0..63], Bs = Ps[64..127]
    int tq = tid & 15, tk = tid >> 4;                  // 16 x 16
    float best[4][4];
    #pragma unroll
    for (int i = 0; i < 4; i++)
        #pragma unroll
        for (int j = 0; j < 4; j++) best[i][j] = -3.402823466e38f;
    #pragma unroll 4
    for (int v = 0; v < 64; v++) {
        float a[4], bb[4];
        #pragma unroll
        for (int i = 0; i < 4; i++) {
            a[i]  = su.Ps[tq + 16 * i][v];
            bb[i] = su.Ps[64 + tk + 16 * i][v];
        }
        #pragma unroll
        for (int i = 0; i < 4; i++)
            #pragma unroll
            for (int j = 0; j < 4; j++)
                best[i][j] = fmaxf(best[i][j], a[i] + bb[j]);
    }
    #pragma unroll
    for (int i = 0; i < 4; i++)
        #pragma unroll
        for (int j = 0; j < 4; j++) {
            int q = tq + 16 * i, kk = tk + 16 * j;
            int pair = (bh * 64 + q) * 64 + kk;
            g_pv[(pair * VSPL + vc) & M_P] = best[i][j];
        }
}

// ---------------- K4a: per-pair merge + index recovery + ws -------------------
__global__ void k4a_merge(float* __restrict__ out, int n_out) {
    int p = blockIdx.x * 256 + threadIdx.x;            // 0..65535
    int bh = p >> 12, q = (p >> 6) & 63, kk = p & 63;

    float bv = -3.402823466e38f; int sp = 0;
    #pragma unroll 4
    for (int j = 0; j < VSPL; j += 4) {
        float4 v4 = *(const float4*)&g_pv[((p * VSPL) + j) & (M_P & ~3u)];
        if (v4.x > bv) { bv = v4.x; sp = j; }
        if (v4.y > bv) { bv = v4.y; sp = j + 1; }
        if (v4.z > bv) { bv = v4.z; sp = j + 2; }
        if (v4.w > bv) { bv = v4.w; sp = j + 3; }
    }
    int rowA = (bh * 64 + q)  * VOC + sp * 64;
    int rowB = (bh * 64 + kk) * VOC + sp * 64;
    int bi = -1;
    #pragma unroll 4
    for (int v = 0; v < 64; v += 4) {
        float4 a4 = *(const float4*)&g_A [(rowA + v) & (M_AB & ~3u)];
        float4 b4 = *(const float4*)&g_Bm[(rowB + v) & (M_AB & ~3u)];
        if (bi < 0) {
            if      (a4.x + b4.x == bv) bi = sp * 64 + v;
            else if (a4.y + b4.y == bv) bi = sp * 64 + v + 1;
            else if (a4.z + b4.z == bv) bi = sp * 64 + v + 2;
            else if (a4.w + b4.w == bv) bi = sp * 64 + v + 3;
        }
    }
    if (bi < 0) bi = 0;                                // unreachable; safety

    float n2 = g_nq[(bh * 64 + q) & M_NRM] + g_nk[(bh * 64 + kk) & M_NRM]
             + 2.0f * g_G[((bh * 64 + q) * 64 + kk) & M_G];
    float ws = bv * rsqrtf(fmaxf(n2, 1e-12f));
    g_ws[p & M_W] = ws;
    g_id[p & M_W] = bi;

    int b = bh >> 3, h = bh & 7;
    int oidx = ((b * 64 + q) * 64 + kk) * 8 + h;
    if (65536 + oidx < n_out)  out[65536  + oidx] = (float)bi;  // out_ids
    if (131072 + oidx < n_out) out[131072 + oidx] = ws;         // r3_scores
}

// ---------------- K4b: weighted sum + final LN (4 groups per block) -----------
__global__ void k4b_final(const float* __restrict__ lng, const float* __restrict__ lnb,
                          float* __restrict__ out, int n_out) {
    __shared__ float sws[4][64];
    __shared__ int   sid[4][64];
    __shared__ float sred[4][64];
    int grp = threadIdx.x >> 6;                        // 0..3
    int t   = threadIdx.x & 63;
    int idx = blockIdx.x * 4 + grp;                    // 0..1023 = (b,q,h)
    int b = idx >> 9, q = (idx >> 3) & 63, h = idx & 7;
    int bh = b * 8 + h;
    int pair = (bh * 64 + q) * 64 + t;
    sws[grp][t] = g_ws[pair & M_W];
    sid[grp][t] = g_id[pair & M_W];
    __syncthreads();
    int e = t;
    float acc = 0.f;
    #pragma unroll 4
    for (int j = 0; j < 64; j++)
        acc += sws[grp][j] * g_dp[(sid[grp][j] * DKV + e) & M_DICT];
    acc *= (1.0f / 64.0f);
    sred[grp][t] = acc; __syncthreads();
    #pragma unroll
    for (int s = 32; s > 0; s >>= 1) {
        if (t < s) sred[grp][t] += sred[grp][t + s];
        __syncthreads();
    }
    float mean = sred[grp][0] * (1.0f / 64.0f);
    __syncthreads();
    float diff = acc - mean;
    sred[grp][t] = diff * diff; __syncthreads();
    #pragma unroll
    for (int s = 32; s > 0; s >>= 1) {
        if (t < s) sred[grp][t] += sred[grp][t + s];
        __syncthreads();
    }
    float var = sred[grp][0] * (1.0f / 64.0f);
    float r = diff * rsqrtf(var + 1e-6f) * lng[e & 63] + lnb[e & 63];
    int widx = (bh * 64 + q) * 64 + e;
    if (widx < n_out) out[widx] = r;                   // [b][h][q][e]
}

// ---------------- fallback: zero-fill output ----------------------------------
__global__ void kz_zero(float* __restrict__ out, int n_out) {
    int i = blockIdx.x * 256 + threadIdx.x;
    if (i < n_out) out[i] = 0.0f;
}

// ---------------- launch ------------------------------------------------------
static bool size_ok(int got, int need_elems) {
    return got == need_elems || got == need_elems * 4;   // elements or bytes
}

extern "C" void kernel_launch(void* const* d_in, const int* in_sizes, int n_in,
                              void* d_out, int out_size) {
    int n_out = out_size;
    if (n_out == 65536 * 4 || n_out == 196608 * 4) n_out >>= 2;
    if (n_out < 0) n_out = 0;
    float* out = (float*)d_out;

    const int SZ_BIG = BSX * QL * INNER;       // 65536
    const int SZ_WI  = 2 * INNER * INNER;      // 524288
    const int SZ_DI  = VOC * DKV;              // 262144
    const int SZ_OW  = DKV * DKV;              // 4096
    const int SZ_V   = DKV;                    // 64

    const float *query = 0, *key = 0, *qpe = 0, *kpe = 0, *wi = 0, *dict = 0,
                *ow = 0, *vg = 0, *vb = 0, *lg = 0, *lb = 0;
    bool mapped = false;

    if (n_in >= 11) {
        const int sig[11] = {SZ_BIG, SZ_BIG, SZ_BIG, SZ_BIG, SZ_WI, SZ_DI,
                             SZ_V, SZ_V, SZ_OW, SZ_V, SZ_V};
        bool ok = true;
        for (int i = 0; i < 11; i++) ok = ok && size_ok(in_sizes[i], sig[i]);
        if (ok) {
            query = (const float*)d_in[0];  key = (const float*)d_in[1];
            qpe   = (const float*)d_in[2];  kpe = (const float*)d_in[3];
            wi    = (const float*)d_in[4];  dict = (const float*)d_in[5];
            vg    = (const float*)d_in[6];  vb  = (const float*)d_in[7];
            ow    = (const float*)d_in[8];  lg  = (const float*)d_in[9];
            lb    = (const float*)d_in[10];
            mapped = true;
        }
        if (!mapped) {
            const int alp[11] = {SZ_BIG, SZ_BIG, SZ_V, SZ_V, SZ_BIG, SZ_BIG,
                                 SZ_DI, SZ_V, SZ_V, SZ_OW, SZ_WI};
            bool ok2 = true;
            for (int i = 0; i < 11; i++) ok2 = ok2 && size_ok(in_sizes[i], alp[i]);
            if (ok2) {
                key  = (const float*)d_in[0];  kpe = (const float*)d_in[1];
                lb   = (const float*)d_in[2];  lg  = (const float*)d_in[3];
                qpe  = (const float*)d_in[4];  query = (const float*)d_in[5];
                dict = (const float*)d_in[6];  vb  = (const float*)d_in[7];
                vg   = (const float*)d_in[8];  ow  = (const float*)d_in[9];
                wi   = (const float*)d_in[10];
                mapped = true;
            }
        }
    }

    if (!mapped) {
        if (n_out > 0) kz_zero<<<(n_out + 255) / 256, 256>>>(out, n_out);
        return;
    }

    k0_dict   <<<64, 256>>>(dict, vg, vb, ow);
    k1_proj   <<<dim3(8, 16, 2), 128>>>(query, key, qpe, kpe, wi);
    k1c_gram  <<<16, 256>>>();
    k23_ab_max<<<dim3(64, 16), 256>>>();
    k4a_merge <<<256, 256>>>(out, n_out);
    k4b_final <<<256, 256>>>(lg, lb, out, n_out);
}

// round 10
// speedup vs baseline: 1.3805x; 1.0709x over previous
#include <cuda_runtime.h>
#include <math.h>

// Problem constants
#define BSX   2
#define QL    64
#define KLN   64
#define NH    8
#define DKV   64
#define INNER 512
#define VOC   4096
#define NBH   16          // BSX * NH
#define VSPL  64          // v-range splits (64 v each)

// Masks (all scratch arrays are power-of-2 element counts)
#define M_PROJ 0xFFFFu     // 65536
#define M_DICT 0x3FFFFu    // 262144
#define M_AB   0x3FFFFFu   // 4194304
#define M_NRM  0x3FFu      // 1024
#define M_G    0xFFFFu     // 65536
#define M_P    0x3FFFFFu   // 4194304
#define M_W    0xFFFFu     // 65536

// ---------------- scratch (device globals; no allocation allowed) -------------
__device__ float g_qproj[BSX * QL * INNER];        // 65536
__device__ float g_kproj[BSX * KLN * INNER];       // 65536
__device__ float g_dnT[DKV * VOC];                 // l2 dict [d][v]  262144
__device__ float g_dp[VOC * DKV];                  // LN(dict)@O      262144
__device__ float g_A[NBH * QL * VOC];              // 4194304
__device__ float g_Bm[NBH * KLN * VOC];            // 4194304
__device__ float g_nq[NBH * QL];                   // 1024
__device__ float g_nk[NBH * KLN];                  // 1024
__device__ float g_G[NBH * QL * KLN];              // 65536
__device__ float g_pv[NBH * QL * KLN * VSPL];      // 4194304
__device__ float g_ws[NBH * QL * KLN];             // 65536
__device__ int   g_id[NBH * QL * KLN];             // 65536

// ---------------- K0: dict preprocessing (l2norm(T) + LN@O) -------------------
__global__ void k0_dict(const float* __restrict__ dict,
                        const float* __restrict__ vg,
                        const float* __restrict__ vb,
                        const float* __restrict__ O) {
    __shared__ float sn[64][65];                       // [d][vlocal]
    int l = threadIdx.x & 31, warp = threadIdx.x >> 5;
    int v0 = blockIdx.x * 64;
    #pragma unroll
    for (int i = 0; i < 8; i++) {
        int vl = warp * 8 + i;
        int r = v0 + vl;
        float x0 = dict[(r * DKV + l) & M_DICT];
        float x1 = dict[(r * DKV + 32 + l) & M_DICT];

        float s = x0 * x0 + x1 * x1;
        #pragma unroll
        for (int o = 16; o > 0; o >>= 1) s += __shfl_xor_sync(0xffffffffu, s, o);
        float inv = rsqrtf(fmaxf(s, 1e-12f));
        sn[l][vl]      = x0 * inv;
        sn[l + 32][vl] = x1 * inv;

        float m = x0 + x1;
        #pragma unroll
        for (int o = 16; o > 0; o >>= 1) m += __shfl_xor_sync(0xffffffffu, m, o);
        m *= (1.0f / 64.0f);
        float d0 = x0 - m, d1 = x1 - m;
        float v = d0 * d0 + d1 * d1;
        #pragma unroll
        for (int o = 16; o > 0; o >>= 1) v += __shfl_xor_sync(0xffffffffu, v, o);
        v *= (1.0f / 64.0f);
        float rs = rsqrtf(v + 1e-6f);
        float ln0 = d0 * rs * vg[l & 63]        + vb[l & 63];
        float ln1 = d1 * rs * vg[(l + 32) & 63] + vb[(l + 32) & 63];

        float a0 = 0.f, a1 = 0.f;
        #pragma unroll
        for (int d2 = 0; d2 < 32; d2++) {
            float t = __shfl_sync(0xffffffffu, ln0, d2);
            a0 += t * O[(d2 * 64 + l) & 4095];
            a1 += t * O[(d2 * 64 + 32 + l) & 4095];
        }
        #pragma unroll
        for (int d2 = 0; d2 < 32; d2++) {
            float t = __shfl_sync(0xffffffffu, ln1, d2);
            a0 += t * O[((32 + d2) * 64 + l) & 4095];
            a1 += t * O[((32 + d2) * 64 + 32 + l) & 4095];
        }
        g_dp[(r * DKV + l) & M_DICT]      = a0;
        g_dp[(r * DKV + 32 + l) & M_DICT] = a1;
    }
    __syncthreads();
    for (int i = threadIdx.x; i < 64 * 64; i += 256) {
        int d = i >> 6, vl = i & 63;
        g_dnT[(d * VOC + v0 + vl) & M_DICT] = sn[d][vl];
    }
}

// ---------------- K1: q_proj / k_proj GEMM ------------------------------------
__global__ void k1_proj(const float* __restrict__ q, const float* __restrict__ k,
                        const float* __restrict__ qpe, const float* __restrict__ kpe,
                        const float* __restrict__ wi) {
    __shared__ __align__(16) float xs[8][INNER];
    int side = blockIdx.z;
    const float* xin = side ? k   : q;
    const float* pin = side ? kpe : qpe;
    const float* W   = wi + side * (INNER * INNER);
    float* out = side ? g_kproj : g_qproj;
    int m0 = blockIdx.y * 8;
    int tid = threadIdx.x;                             // 128 threads
    for (int i = tid; i < 8 * INNER; i += 128) {
        int r = i >> 9, d = i & 511;
        int gidx = ((m0 + r) * INNER + d) & M_PROJ;
        xs[r][d] = xin[gidx] + pin[gidx];
    }
    __syncthreads();
    int e  = blockIdx.x * 64 + (tid & 63);             // 0..511
    int r0 = (tid >> 6) * 4;                           // 0 or 4
    float acc[4] = {};
    for (int d = 0; d < INNER; d += 4) {
        float w0 = W[((d + 0) * INNER + e) & 0x3FFFF];
        float w1 = W[((d + 1) * INNER + e) & 0x3FFFF];
        float w2 = W[((d + 2) * INNER + e) & 0x3FFFF];
        float w3 = W[((d + 3) * INNER + e) & 0x3FFFF];
        #pragma unroll
        for (int r = 0; r < 4; r++) {
            float4 xv = *(const float4*)&xs[r0 + r][d];
            acc[r] += xv.x * w0 + xv.y * w1 + xv.z * w2 + xv.w * w3;
        }
    }
    #pragma unroll
    for (int r = 0; r < 4; r++)
        out[((m0 + r0 + r) * INNER + e) & M_PROJ] = acc[r];
}

// ---------------- K1c: per-head Gram + norms; grid (4 qt, 16 bh) --------------
__global__ void k1c_gram() {
    __shared__ float qs[16][65];
    __shared__ float ks[64][65];
    int qt = blockIdx.x;                               // 0..3
    int bh = blockIdx.y;                               // 0..15
    int b = bh >> 3, h = bh & 7;
    int tid = threadIdx.x;                             // 256
    for (int i = tid; i < 16 * 64; i += 256) {
        int r = i >> 6, d = i & 63;
        qs[r][d] = g_qproj[((b * 64 + qt * 16 + r) * INNER + h * 64 + d) & M_PROJ];
    }
    for (int i = tid; i < 64 * 64; i += 256) {
        int r = i >> 6, d = i & 63;
        ks[r][d] = g_kproj[((b * 64 + r) * INNER + h * 64 + d) & M_PROJ];
    }
    __syncthreads();
    int qq = tid >> 4;                                 // 0..15
    int kb = (tid & 15) * 4;                           // 4 k each
    float acc[4] = {};
    for (int d = 0; d < 64; d++) {
        float a = qs[qq][d];
        #pragma unroll
        for (int j = 0; j < 4; j++) acc[j] += a * ks[kb + j][d];
    }
    #pragma unroll
    for (int j = 0; j < 4; j++)
        g_G[((bh * 64 + qt * 16 + qq) * 64 + kb + j) & M_G] = acc[j];
    if (tid < 16) {
        float s = 0.f;
        #pragma unroll 8
        for (int d = 0; d < 64; d++) { float x = qs[tid][d]; s += x * x; }
        g_nq[(bh * 64 + qt * 16 + tid) & M_NRM] = s;
    } else if (qt == 0 && tid >= 64 && tid < 128) {
        int r = tid - 64;
        float s = 0.f;
        #pragma unroll 8
        for (int d = 0; d < 64; d++) { float x = ks[r][d]; s += x * x; }
        g_nk[(bh * 64 + r) & M_NRM] = s;
    }
}

// ---------------- K23: fused GEMM (A & B rows) + per-chunk max ----------------
// block = (64-v chunk, bh); 256 threads.
__global__ void k23_ab_max() {
    __shared__ union SU {
        struct { float xsT[32][132]; float dst[32][68]; } p1;  // GEMM inputs
        float Ps[128][68];                                     // GEMM outputs (16B rows)
    } su;
    int vc = blockIdx.x;                               // 0..63
    int bh = blockIdx.y;                               // 0..15
    int b = bh >> 3, h = bh & 7;
    int v0 = vc * 64;
    int tid = threadIdx.x;                             // 256
    int tv = tid & 7, tr = tid >> 3;                   // 8 v-groups x 32 row-groups
    float acc[4][8] = {};

    #pragma unroll
    for (int c = 0; c < 2; c++) {
        __syncthreads();
        for (int i = tid; i < 128 * 8; i += 256) {
            int r = i >> 3, d4 = (i & 7) * 4;
            const float* src = (r < 64) ? g_qproj : g_kproj;
            int g = ((b * 64 + (r & 63)) * INNER + h * 64 + c * 32 + d4) & (M_PROJ & ~3u);
            float4 vv = *(const float4*)&src[g];
            su.p1.xsT[d4 + 0][r] = vv.x; su.p1.xsT[d4 + 1][r] = vv.y;
            su.p1.xsT[d4 + 2][r] = vv.z; su.p1.xsT[d4 + 3][r] = vv.w;
        }
        for (int i = tid; i < 32 * 16; i += 256) {
            int d = i >> 4, m4 = (i & 15) * 4;
            int g = ((c * 32 + d) * VOC + v0 + m4) & (M_DICT & ~3u);
            *(float4*)&su.p1.dst[d][m4] = *(const float4*)&g_dnT[g];
        }
        __syncthreads();
        #pragma unroll 4
        for (int d = 0; d < 32; d++) {
            float4 xv  = *(const float4*)&su.p1.xsT[d][tr * 4];
            float4 dv0 = *(const float4*)&su.p1.dst[d][tv * 8];
            float4 dv1 = *(const float4*)&su.p1.dst[d][tv * 8 + 4];
            float xa[4] = {xv.x, xv.y, xv.z, xv.w};
            #pragma unroll
            for (int i = 0; i < 4; i++) {
                float a = xa[i];
                acc[i][0] += a * dv0.x; acc[i][1] += a * dv0.y;
                acc[i][2] += a * dv0.z; acc[i][3] += a * dv0.w;
                acc[i][4] += a * dv1.x; acc[i][5] += a * dv1.y;
                acc[i][6] += a * dv1.z; acc[i][7] += a * dv1.w;
            }
        }
    }
    __syncthreads();                                   // done with p1; reuse as Ps
    #pragma unroll
    for (int i = 0; i < 4; i++) {
        int r = tr * 4 + i;                            // 0..127
        *(float4*)&su.Ps[r][tv * 8]     = make_float4(acc[i][0], acc[i][1], acc[i][2], acc[i][3]);
        *(float4*)&su.Ps[r][tv * 8 + 4] = make_float4(acc[i][4], acc[i][5], acc[i][6], acc[i][7]);
        float* out = (r < 64) ? g_A : g_Bm;
        int base = ((bh * 64 + (r & 63)) * VOC + v0 + tv * 8) & (M_AB & ~3u);
        *(float4*)&out[base]     = make_float4(acc[i][0], acc[i][1], acc[i][2], acc[i][3]);
        *(float4*)&out[base + 4] = make_float4(acc[i][4], acc[i][5], acc[i][6], acc[i][7]);
    }
    __syncthreads();

    // max phase: rows 0..63 = A(q), 64..127 = B(k); float4 over v
    int tq = tid & 15, tk = tid >> 4;                  // 16 x 16
    float best[4][4];
    #pragma unroll
    for (int i = 0; i < 4; i++)
        #pragma unroll
        for (int j = 0; j < 4; j++) best[i][j] = -3.402823466e38f;
    for (int v = 0; v < 64; v += 4) {
        float4 a4[4], b4[4];
        #pragma unroll
        for (int i = 0; i < 4; i++) {
            a4[i] = *(const float4*)&su.Ps[tq + 16 * i][v];
            b4[i] = *(const float4*)&su.Ps[64 + tk + 16 * i][v];
        }
        #pragma unroll
        for (int i = 0; i < 4; i++)
            #pragma unroll
            for (int j = 0; j < 4; j++) {
                float m0 = fmaxf(a4[i].x + b4[j].x, a4[i].y + b4[j].y);
                float m1 = fmaxf(a4[i].z + b4[j].z, a4[i].w + b4[j].w);
                best[i][j] = fmaxf(best[i][j], fmaxf(m0, m1));
            }
    }
    #pragma unroll
    for (int i = 0; i < 4; i++)
        #pragma unroll
        for (int j = 0; j < 4; j++) {
            int q = tq + 16 * i, kk = tk + 16 * j;
            int pair = (bh * 64 + q) * 64 + kk;
            g_pv[(pair * VSPL + vc) & M_P] = best[i][j];
        }
}

// ---------------- K4a: per-pair merge + index recovery + ws -------------------
__global__ void k4a_merge(float* __restrict__ out, int n_out) {
    int p = blockIdx.x * 256 + threadIdx.x;            // 0..65535
    int bh = p >> 12, q = (p >> 6) & 63, kk = p & 63;

    float bv = -3.402823466e38f; int sp = 0;
    #pragma unroll 4
    for (int j = 0; j < VSPL; j += 4) {
        float4 v4 = *(const float4*)&g_pv[((p * VSPL) + j) & (M_P & ~3u)];
        if (v4.x > bv) { bv = v4.x; sp = j; }
        if (v4.y > bv) { bv = v4.y; sp = j + 1; }
        if (v4.z > bv) { bv = v4.z; sp = j + 2; }
        if (v4.w > bv) { bv = v4.w; sp = j + 3; }
    }
    int rowA = (bh * 64 + q)  * VOC + sp * 64;
    int rowB = (bh * 64 + kk) * VOC + sp * 64;
    int bi = -1;
    #pragma unroll 4
    for (int v = 0; v < 64; v += 4) {
        float4 a4 = *(const float4*)&g_A [(rowA + v) & (M_AB & ~3u)];
        float4 b4 = *(const float4*)&g_Bm[(rowB + v) & (M_AB & ~3u)];
        if (bi < 0) {
            if      (a4.x + b4.x == bv) bi = sp * 64 + v;
            else if (a4.y + b4.y == bv) bi = sp * 64 + v + 1;
            else if (a4.z + b4.z == bv) bi = sp * 64 + v + 2;
            else if (a4.w + b4.w == bv) bi = sp * 64 + v + 3;
        }
    }
    if (bi < 0) bi = 0;                                // unreachable; safety

    float n2 = g_nq[(bh * 64 + q) & M_NRM] + g_nk[(bh * 64 + kk) & M_NRM]
             + 2.0f * g_G[((bh * 64 + q) * 64 + kk) & M_G];
    float ws = bv * rsqrtf(fmaxf(n2, 1e-12f));
    g_ws[p & M_W] = ws;
    g_id[p & M_W] = bi;

    int b = bh >> 3, h = bh & 7;
    int oidx = ((b * 64 + q) * 64 + kk) * 8 + h;
    if (65536 + oidx < n_out)  out[65536  + oidx] = (float)bi;  // out_ids
    if (131072 + oidx < n_out) out[131072 + oidx] = ws;         // r3_scores
}

// ---------------- K4b: weighted sum + final LN (4 groups per block) -----------
__global__ void k4b_final(const float* __restrict__ lng, const float* __restrict__ lnb,
                          float* __restrict__ out, int n_out) {
    __shared__ float sws[4][64];
    __shared__ int   sid[4][64];
    __shared__ float sred[4][64];
    int grp = threadIdx.x >> 6;                        // 0..3
    int t   = threadIdx.x & 63;
    int idx = blockIdx.x * 4 + grp;                    // 0..1023 = (b,q,h)
    int b = idx >> 9, q = (idx >> 3) & 63, h = idx & 7;
    int bh = b * 8 + h;
    int pair = (bh * 64 + q) * 64 + t;
    sws[grp][t] = g_ws[pair & M_W];
    sid[grp][t] = g_id[pair & M_W];
    __syncthreads();
    int e = t;
    float acc = 0.f;
    #pragma unroll 4
    for (int j = 0; j < 64; j++)
        acc += sws[grp][j] * g_dp[(sid[grp][j] * DKV + e) & M_DICT];
    acc *= (1.0f / 64.0f);
    sred[grp][t] = acc; __syncthreads();
    #pragma unroll
    for (int s = 32; s > 0; s >>= 1) {
        if (t < s) sred[grp][t] += sred[grp][t + s];
        __syncthreads();
    }
    float mean = sred[grp][0] * (1.0f / 64.0f);
    __syncthreads();
    float diff = acc - mean;
    sred[grp][t] = diff * diff; __syncthreads();
    #pragma unroll
    for (int s = 32; s > 0; s >>= 1) {
        if (t < s) sred[grp][t] += sred[grp][t + s];
        __syncthreads();
    }
    float var = sred[grp][0] * (1.0f / 64.0f);
    float r = diff * rsqrtf(var + 1e-6f) * lng[e & 63] + lnb[e & 63];
    int widx = (bh * 64 + q) * 64 + e;
    if (widx < n_out) out[widx] = r;                   // [b][h][q][e]
}

// ---------------- fallback: zero-fill output ----------------------------------
__global__ void kz_zero(float* __restrict__ out, int n_out) {
    int i = blockIdx.x * 256 + threadIdx.x;
    if (i < n_out) out[i] = 0.0f;
}

// ---------------- launch ------------------------------------------------------
static bool size_ok(int got, int need_elems) {
    return got == need_elems || got == need_elems * 4;   // elements or bytes
}

extern "C" void kernel_launch(void* const* d_in, const int* in_sizes, int n_in,
                              void* d_out, int out_size) {
    int n_out = out_size;
    if (n_out == 65536 * 4 || n_out == 196608 * 4) n_out >>= 2;
    if (n_out < 0) n_out = 0;
    float* out = (float*)d_out;

    const int SZ_BIG = BSX * QL * INNER;       // 65536
    const int SZ_WI  = 2 * INNER * INNER;      // 524288
    const int SZ_DI  = VOC * DKV;              // 262144
    const int SZ_OW  = DKV * DKV;              // 4096
    const int SZ_V   = DKV;                    // 64

    const float *query = 0, *key = 0, *qpe = 0, *kpe = 0, *wi = 0, *dict = 0,
                *ow = 0, *vg = 0, *vb = 0, *lg = 0, *lb = 0;
    bool mapped = false;

    if (n_in >= 11) {
        const int sig[11] = {SZ_BIG, SZ_BIG, SZ_BIG, SZ_BIG, SZ_WI, SZ_DI,
                             SZ_V, SZ_V, SZ_OW, SZ_V, SZ_V};
        bool ok = true;
        for (int i = 0; i < 11; i++) ok = ok && size_ok(in_sizes[i], sig[i]);
        if (ok) {
            query = (const float*)d_in[0];  key = (const float*)d_in[1];
            qpe   = (const float*)d_in[2];  kpe = (const float*)d_in[3];
            wi    = (const float*)d_in[4];  dict = (const float*)d_in[5];
            vg    = (const float*)d_in[6];  vb  = (const float*)d_in[7];
            ow    = (const float*)d_in[8];  lg  = (const float*)d_in[9];
            lb    = (const float*)d_in[10];
            mapped = true;
        }
        if (!mapped) {
            const int alp[11] = {SZ_BIG, SZ_BIG, SZ_V, SZ_V, SZ_BIG, SZ_BIG,
                                 SZ_DI, SZ_V, SZ_V, SZ_OW, SZ_WI};
            bool ok2 = true;
            for (int i = 0; i < 11; i++) ok2 = ok2 && size_ok(in_sizes[i], alp[i]);
            if (ok2) {
                key  = (const float*)d_in[0];  kpe = (const float*)d_in[1];
                lb   = (const float*)d_in[2];  lg  = (const float*)d_in[3];
                qpe  = (const float*)d_in[4];  query = (const float*)d_in[5];
                dict = (const float*)d_in[6];  vb  = (const float*)d_in[7];
                vg   = (const float*)d_in[8];  ow  = (const float*)d_in[9];
                wi   = (const float*)d_in[10];
                mapped = true;
            }
        }
    }

    if (!mapped) {
        if (n_out > 0) kz_zero<<<(n_out + 255) / 256, 256>>>(out, n_out);
        return;
    }

    k0_dict   <<<64, 256>>>(dict, vg, vb, ow);
    k1_proj   <<<dim3(8, 16, 2), 128>>>(query, key, qpe, kpe, wi);
    k1c_gram  <<<dim3(4, 16), 256>>>();
    k23_ab_max<<<dim3(64, 16), 256>>>();
    k4a_merge <<<256, 256>>>(out, n_out);
    k4b_final <<<256, 256>>>(lg, lb, out, n_out);
}

// round 11
// speedup vs baseline: 1.3995x; 1.0138x over previous
#include <cuda_runtime.h>
#include <math.h>

// Problem constants
#define BSX   2
#define QL    64
#define KLN   64
#define NH    8
#define DKV   64
#define INNER 512
#define VOC   4096
#define NBH   16          // BSX * NH
#define VSPL  64          // v-range splits (64 v each)

// Masks (all scratch arrays are power-of-2 element counts)
#define M_PROJ 0xFFFFu     // 65536
#define M_DICT 0x3FFFFu    // 262144
#define M_AB   0x3FFFFFu   // 4194304
#define M_NRM  0x3FFu      // 1024
#define M_G    0xFFFFu     // 65536
#define M_P    0x3FFFFFu   // 4194304
#define M_W    0xFFFFu     // 65536

typedef unsigned long long u64;
#define ADD_F32X2(out, a, b) \
    asm("add.rn.f32x2 %0, %1, %2;" : "=l"(out) : "l"(a), "l"(b))

// ---------------- scratch (device globals; no allocation allowed) -------------
__device__ float g_qproj[BSX * QL * INNER];        // 65536
__device__ float g_kproj[BSX * KLN * INNER];       // 65536
__device__ float g_dnT[DKV * VOC];                 // l2 dict [d][v]  262144
__device__ float g_dp[VOC * DKV];                  // LN(dict)@O      262144
__device__ float g_A[NBH * QL * VOC];              // 4194304
__device__ float g_Bm[NBH * KLN * VOC];            // 4194304
__device__ float g_nq[NBH * QL];                   // 1024
__device__ float g_nk[NBH * KLN];                  // 1024
__device__ float g_G[NBH * QL * KLN];              // 65536
__device__ float g_pv[NBH * QL * KLN * VSPL];      // 4194304
__device__ float g_ws[NBH * QL * KLN];             // 65536
__device__ int   g_id[NBH * QL * KLN];             // 65536

// ---------------- K0: dict preprocessing (l2norm(T) + LN@O) -------------------
__global__ void k0_dict(const float* __restrict__ dict,
                        const float* __restrict__ vg,
                        const float* __restrict__ vb,
                        const float* __restrict__ O) {
    __shared__ float sn[64][65];                       // [d][vlocal]
    int l = threadIdx.x & 31, warp = threadIdx.x >> 5;
    int v0 = blockIdx.x * 64;
    #pragma unroll
    for (int i = 0; i < 8; i++) {
        int vl = warp * 8 + i;
        int r = v0 + vl;
        float x0 = dict[(r * DKV + l) & M_DICT];
        float x1 = dict[(r * DKV + 32 + l) & M_DICT];

        float s = x0 * x0 + x1 * x1;
        #pragma unroll
        for (int o = 16; o > 0; o >>= 1) s += __shfl_xor_sync(0xffffffffu, s, o);
        float inv = rsqrtf(fmaxf(s, 1e-12f));
        sn[l][vl]      = x0 * inv;
        sn[l + 32][vl] = x1 * inv;

        float m = x0 + x1;
        #pragma unroll
        for (int o = 16; o > 0; o >>= 1) m += __shfl_xor_sync(0xffffffffu, m, o);
        m *= (1.0f / 64.0f);
        float d0 = x0 - m, d1 = x1 - m;
        float v = d0 * d0 + d1 * d1;
        #pragma unroll
        for (int o = 16; o > 0; o >>= 1) v += __shfl_xor_sync(0xffffffffu, v, o);
        v *= (1.0f / 64.0f);
        float rs = rsqrtf(v + 1e-6f);
        float ln0 = d0 * rs * vg[l & 63]        + vb[l & 63];
        float ln1 = d1 * rs * vg[(l + 32) & 63] + vb[(l + 32) & 63];

        float a0 = 0.f, a1 = 0.f;
        #pragma unroll
        for (int d2 = 0; d2 < 32; d2++) {
            float t = __shfl_sync(0xffffffffu, ln0, d2);
            a0 += t * O[(d2 * 64 + l) & 4095];
            a1 += t * O[(d2 * 64 + 32 + l) & 4095];
        }
        #pragma unroll
        for (int d2 = 0; d2 < 32; d2++) {
            float t = __shfl_sync(0xffffffffu, ln1, d2);
            a0 += t * O[((32 + d2) * 64 + l) & 4095];
            a1 += t * O[((32 + d2) * 64 + 32 + l) & 4095];
        }
        g_dp[(r * DKV + l) & M_DICT]      = a0;
        g_dp[(r * DKV + 32 + l) & M_DICT] = a1;
    }
    __syncthreads();
    for (int i = threadIdx.x; i < 64 * 64; i += 256) {
        int d = i >> 6, vl = i & 63;
        g_dnT[(d * VOC + v0 + vl) & M_DICT] = sn[d][vl];
    }
}

// ---------------- K1: q_proj / k_proj GEMM ------------------------------------
__global__ void k1_proj(const float* __restrict__ q, const float* __restrict__ k,
                        const float* __restrict__ qpe, const float* __restrict__ kpe,
                        const float* __restrict__ wi) {
    __shared__ __align__(16) float xs[8][INNER];
    int side = blockIdx.z;
    const float* xin = side ? k   : q;
    const float* pin = side ? kpe : qpe;
    const float* W   = wi + side * (INNER * INNER);
    float* out = side ? g_kproj : g_qproj;
    int m0 = blockIdx.y * 8;
    int tid = threadIdx.x;                             // 128 threads
    for (int i = tid; i < 8 * INNER; i += 128) {
        int r = i >> 9, d = i & 511;
        int gidx = ((m0 + r) * INNER + d) & M_PROJ;
        xs[r][d] = xin[gidx] + pin[gidx];
    }
    __syncthreads();
    int e  = blockIdx.x * 64 + (tid & 63);             // 0..511
    int r0 = (tid >> 6) * 4;                           // 0 or 4
    float acc[4] = {};
    for (int d = 0; d < INNER; d += 4) {
        float w0 = W[((d + 0) * INNER + e) & 0x3FFFF];
        float w1 = W[((d + 1) * INNER + e) & 0x3FFFF];
        float w2 = W[((d + 2) * INNER + e) & 0x3FFFF];
        float w3 = W[((d + 3) * INNER + e) & 0x3FFFF];
        #pragma unroll
        for (int r = 0; r < 4; r++) {
            float4 xv = *(const float4*)&xs[r0 + r][d];
            acc[r] += xv.x * w0 + xv.y * w1 + xv.z * w2 + xv.w * w3;
        }
    }
    #pragma unroll
    for (int r = 0; r < 4; r++)
        out[((m0 + r0 + r) * INNER + e) & M_PROJ] = acc[r];
}

// ---------------- K1c: per-head Gram + norms; grid (4 qt, 16 bh) --------------
__global__ void k1c_gram() {
    __shared__ float qs[16][65];
    __shared__ float ks[64][65];
    int qt = blockIdx.x;                               // 0..3
    int bh = blockIdx.y;                               // 0..15
    int b = bh >> 3, h = bh & 7;
    int tid = threadIdx.x;                             // 256
    for (int i = tid; i < 16 * 64; i += 256) {
        int r = i >> 6, d = i & 63;
        qs[r][d] = g_qproj[((b * 64 + qt * 16 + r) * INNER + h * 64 + d) & M_PROJ];
    }
    for (int i = tid; i < 64 * 64; i += 256) {
        int r = i >> 6, d = i & 63;
        ks[r][d] = g_kproj[((b * 64 + r) * INNER + h * 64 + d) & M_PROJ];
    }
    __syncthreads();
    int qq = tid >> 4;                                 // 0..15
    int kb = (tid & 15) * 4;                           // 4 k each
    float acc[4] = {};
    for (int d = 0; d < 64; d++) {
        float a = qs[qq][d];
        #pragma unroll
        for (int j = 0; j < 4; j++) acc[j] += a * ks[kb + j][d];
    }
    #pragma unroll
    for (int j = 0; j < 4; j++)
        g_G[((bh * 64 + qt * 16 + qq) * 64 + kb + j) & M_G] = acc[j];
    if (tid < 16) {
        float s = 0.f;
        #pragma unroll 8
        for (int d = 0; d < 64; d++) { float x = qs[tid][d]; s += x * x; }
        g_nq[(bh * 64 + qt * 16 + tid) & M_NRM] = s;
    } else if (qt == 0 && tid >= 64 && tid < 128) {
        int r = tid - 64;
        float s = 0.f;
        #pragma unroll 8
        for (int d = 0; d < 64; d++) { float x = ks[r][d]; s += x * x; }
        g_nk[(bh * 64 + r) & M_NRM] = s;
    }
}

// ---------------- K23: fused GEMM (A & B rows) + per-chunk max ----------------
// block = (64-v chunk, bh); 256 threads; 4 blocks/SM target.
__global__ void __launch_bounds__(256, 4) k23_ab_max() {
    __shared__ union SU {
        struct { float xsT[32][132]; float dst[32][68]; } p1;  // GEMM inputs
        float Ps[128][68];                                     // GEMM outputs (16B rows)
    } su;
    int vc = blockIdx.x;                               // 0..63
    int bh = blockIdx.y;                               // 0..15
    int b = bh >> 3, h = bh & 7;
    int v0 = vc * 64;
    int tid = threadIdx.x;                             // 256
    int tv = tid & 7, tr = tid >> 3;                   // 8 v-groups x 32 row-groups
    float acc[4][8] = {};

    #pragma unroll
    for (int c = 0; c < 2; c++) {
        __syncthreads();
        for (int i = tid; i < 128 * 8; i += 256) {
            int r = i >> 3, d4 = (i & 7) * 4;
            const float* src = (r < 64) ? g_qproj : g_kproj;
            int g = ((b * 64 + (r & 63)) * INNER + h * 64 + c * 32 + d4) & (M_PROJ & ~3u);
            float4 vv = *(const float4*)&src[g];
            su.p1.xsT[d4 + 0][r] = vv.x; su.p1.xsT[d4 + 1][r] = vv.y;
            su.p1.xsT[d4 + 2][r] = vv.z; su.p1.xsT[d4 + 3][r] = vv.w;
        }
        for (int i = tid; i < 32 * 16; i += 256) {
            int d = i >> 4, m4 = (i & 15) * 4;
            int g = ((c * 32 + d) * VOC + v0 + m4) & (M_DICT & ~3u);
            *(float4*)&su.p1.dst[d][m4] = *(const float4*)&g_dnT[g];
        }
        __syncthreads();
        #pragma unroll 4
        for (int d = 0; d < 32; d++) {
            float4 xv  = *(const float4*)&su.p1.xsT[d][tr * 4];
            float4 dv0 = *(const float4*)&su.p1.dst[d][tv * 8];
            float4 dv1 = *(const float4*)&su.p1.dst[d][tv * 8 + 4];
            float xa[4] = {xv.x, xv.y, xv.z, xv.w};
            #pragma unroll
            for (int i = 0; i < 4; i++) {
                float a = xa[i];
                acc[i][0] += a * dv0.x; acc[i][1] += a * dv0.y;
                acc[i][2] += a * dv0.z; acc[i][3] += a * dv0.w;
                acc[i][4] += a * dv1.x; acc[i][5] += a * dv1.y;
                acc[i][6] += a * dv1.z; acc[i][7] += a * dv1.w;
            }
        }
    }
    __syncthreads();                                   // done with p1; reuse as Ps
    #pragma unroll
    for (int i = 0; i < 4; i++) {
        int r = tr * 4 + i;                            // 0..127
        *(float4*)&su.Ps[r][tv * 8]     = make_float4(acc[i][0], acc[i][1], acc[i][2], acc[i][3]);
        *(float4*)&su.Ps[r][tv * 8 + 4] = make_float4(acc[i][4], acc[i][5], acc[i][6], acc[i][7]);
        float* out = (r < 64) ? g_A : g_Bm;
        int base = ((bh * 64 + (r & 63)) * VOC + v0 + tv * 8) & (M_AB & ~3u);
        *(float4*)&out[base]     = make_float4(acc[i][0], acc[i][1], acc[i][2], acc[i][3]);
        *(float4*)&out[base + 4] = make_float4(acc[i][4], acc[i][5], acc[i][6], acc[i][7]);
    }
    __syncthreads();

    // max phase: rows 0..63 = A(q), 64..127 = B(k); packed f32x2 adds
    int tq = tid & 15, tk = tid >> 4;                  // 16 x 16
    float best[4][4];
    #pragma unroll
    for (int i = 0; i < 4; i++)
        #pragma unroll
        for (int j = 0; j < 4; j++) best[i][j] = -3.402823466e38f;
    for (int v = 0; v < 64; v += 4) {
        u64 b0[4], b1[4];
        #pragma unroll
        for (int j = 0; j < 4; j++) {
            ulonglong2 bb = *(const ulonglong2*)&su.Ps[64 + tk + 16 * j][v];
            b0[j] = bb.x; b1[j] = bb.y;
        }
        #pragma unroll
        for (int i = 0; i < 4; i++) {
            ulonglong2 aa = *(const ulonglong2*)&su.Ps[tq + 16 * i][v];
            #pragma unroll
            for (int j = 0; j < 4; j++) {
                u64 c0, c1;
                ADD_F32X2(c0, aa.x, b0[j]);            // 2 candidates
                ADD_F32X2(c1, aa.y, b1[j]);            // 2 candidates
                float2 f0 = *reinterpret_cast<float2*>(&c0);
                float2 f1 = *reinterpret_cast<float2*>(&c1);
                float m = fmaxf(fmaxf(f0.x, f0.y), fmaxf(f1.x, f1.y));
                best[i][j] = fmaxf(best[i][j], m);
            }
        }
    }
    #pragma unroll
    for (int i = 0; i < 4; i++)
        #pragma unroll
        for (int j = 0; j < 4; j++) {
            int q = tq + 16 * i, kk = tk + 16 * j;
            int pair = (bh * 64 + q) * 64 + kk;
            g_pv[(pair * VSPL + vc) & M_P] = best[i][j];
        }
}

// ---------------- K4a: per-pair merge + index recovery + ws -------------------
__global__ void k4a_merge(float* __restrict__ out, int n_out) {
    int p = blockIdx.x * 256 + threadIdx.x;            // 0..65535
    int bh = p >> 12, q = (p >> 6) & 63, kk = p & 63;

    float bv = -3.402823466e38f; int sp = 0;
    #pragma unroll 4
    for (int j = 0; j < VSPL; j += 4) {
        float4 v4 = *(const float4*)&g_pv[((p * VSPL) + j) & (M_P & ~3u)];
        if (v4.x > bv) { bv = v4.x; sp = j; }
        if (v4.y > bv) { bv = v4.y; sp = j + 1; }
        if (v4.z > bv) { bv = v4.z; sp = j + 2; }
        if (v4.w > bv) { bv = v4.w; sp = j + 3; }
    }
    int rowA = (bh * 64 + q)  * VOC + sp * 64;
    int rowB = (bh * 64 + kk) * VOC + sp * 64;
    int bi = -1;
    #pragma unroll 4
    for (int v = 0; v < 64; v += 4) {
        float4 a4 = *(const float4*)&g_A [(rowA + v) & (M_AB & ~3u)];
        float4 b4 = *(const float4*)&g_Bm[(rowB + v) & (M_AB & ~3u)];
        if (bi < 0) {
            if      (a4.x + b4.x == bv) bi = sp * 64 + v;
            else if (a4.y + b4.y == bv) bi = sp * 64 + v + 1;
            else if (a4.z + b4.z == bv) bi = sp * 64 + v + 2;
            else if (a4.w + b4.w == bv) bi = sp * 64 + v + 3;
        }
    }
    if (bi < 0) bi = 0;                                // unreachable; safety

    float n2 = g_nq[(bh * 64 + q) & M_NRM] + g_nk[(bh * 64 + kk) & M_NRM]
             + 2.0f * g_G[((bh * 64 + q) * 64 + kk) & M_G];
    float ws = bv * rsqrtf(fmaxf(n2, 1e-12f));
    g_ws[p & M_W] = ws;
    g_id[p & M_W] = bi;

    int b = bh >> 3, h = bh & 7;
    int oidx = ((b * 64 + q) * 64 + kk) * 8 + h;
    if (65536 + oidx < n_out)  out[65536  + oidx] = (float)bi;  // out_ids
    if (131072 + oidx < n_out) out[131072 + oidx] = ws;         // r3_scores
}

// ---------------- K4b: weighted sum + final LN (4 groups per block) -----------
__global__ void k4b_final(const float* __restrict__ lng, const float* __restrict__ lnb,
                          float* __restrict__ out, int n_out) {
    __shared__ float sws[4][64];
    __shared__ int   sid[4][64];
    __shared__ float sred[4][64];
    int grp = threadIdx.x >> 6;                        // 0..3
    int t   = threadIdx.x & 63;
    int idx = blockIdx.x * 4 + grp;                    // 0..1023 = (b,q,h)
    int b = idx >> 9, q = (idx >> 3) & 63, h = idx & 7;
    int bh = b * 8 + h;
    int pair = (bh * 64 + q) * 64 + t;
    sws[grp][t] = g_ws[pair & M_W];
    sid[grp][t] = g_id[pair & M_W];
    __syncthreads();
    int e = t;
    float acc = 0.f;
    #pragma unroll 4
    for (int j = 0; j < 64; j++)
        acc += sws[grp][j] * g_dp[(sid[grp][j] * DKV + e) & M_DICT];
    acc *= (1.0f / 64.0f);
    sred[grp][t] = acc; __syncthreads();
    #pragma unroll
    for (int s = 32; s > 0; s >>= 1) {
        if (t < s) sred[grp][t] += sred[grp][t + s];
        __syncthreads();
    }
    float mean = sred[grp][0] * (1.0f / 64.0f);
    __syncthreads();
    float diff = acc - mean;
    sred[grp][t] = diff * diff; __syncthreads();
    #pragma unroll
    for (int s = 32; s > 0; s >>= 1) {
        if (t < s) sred[grp][t] += sred[grp][t + s];
        __syncthreads();
    }
    float var = sred[grp][0] * (1.0f / 64.0f);
    float r = diff * rsqrtf(var + 1e-6f) * lng[e & 63] + lnb[e & 63];
    int widx = (bh * 64 + q) * 64 + e;
    if (widx < n_out) out[widx] = r;                   // [b][h][q][e]
}

// ---------------- fallback: zero-fill output ----------------------------------
__global__ void kz_zero(float* __restrict__ out, int n_out) {
    int i = blockIdx.x * 256 + threadIdx.x;
    if (i < n_out) out[i] = 0.0f;
}

// ---------------- launch ------------------------------------------------------
static bool size_ok(int got, int need_elems) {
    return got == need_elems || got == need_elems * 4;   // elements or bytes
}

extern "C" void kernel_launch(void* const* d_in, const int* in_sizes, int n_in,
                              void* d_out, int out_size) {
    int n_out = out_size;
    if (n_out == 65536 * 4 || n_out == 196608 * 4) n_out >>= 2;
    if (n_out < 0) n_out = 0;
    float* out = (float*)d_out;

    const int SZ_BIG = BSX * QL * INNER;       // 65536
    const int SZ_WI  = 2 * INNER * INNER;      // 524288
    const int SZ_DI  = VOC * DKV;              // 262144
    const int SZ_OW  = DKV * DKV;              // 4096
    const int SZ_V   = DKV;                    // 64

    const float *query = 0, *key = 0, *qpe = 0, *kpe = 0, *wi = 0, *dict = 0,
                *ow = 0, *vg = 0, *vb = 0, *lg = 0, *lb = 0;
    bool mapped = false;

    if (n_in >= 11) {
        const int sig[11] = {SZ_BIG, SZ_BIG, SZ_BIG, SZ_BIG, SZ_WI, SZ_DI,
                             SZ_V, SZ_V, SZ_OW, SZ_V, SZ_V};
        bool ok = true;
        for (int i = 0; i < 11; i++) ok = ok && size_ok(in_sizes[i], sig[i]);
        if (ok) {
            query = (const float*)d_in[0];  key = (const float*)d_in[1];
            qpe   = (const float*)d_in[2];  kpe = (const float*)d_in[3];
            wi    = (const float*)d_in[4];  dict = (const float*)d_in[5];
            vg    = (const float*)d_in[6];  vb  = (const float*)d_in[7];
            ow    = (const float*)d_in[8];  lg  = (const float*)d_in[9];
            lb    = (const float*)d_in[10];
            mapped = true;
        }
        if (!mapped) {
            const int alp[11] = {SZ_BIG, SZ_BIG, SZ_V, SZ_V, SZ_BIG, SZ_BIG,
                                 SZ_DI, SZ_V, SZ_V, SZ_OW, SZ_WI};
            bool ok2 = true;
            for (int i = 0; i < 11; i++) ok2 = ok2 && size_ok(in_sizes[i], alp[i]);
            if (ok2) {
                key  = (const float*)d_in[0];  kpe = (const float*)d_in[1];
                lb   = (const float*)d_in[2];  lg  = (const float*)d_in[3];
                qpe  = (const float*)d_in[4];  query = (const float*)d_in[5];
                dict = (const float*)d_in[6];  vb  = (const float*)d_in[7];
                vg   = (const float*)d_in[8];  ow  = (const float*)d_in[9];
                wi   = (const float*)d_in[10];
                mapped = true;
            }
        }
    }

    if (!mapped) {
        if (n_out > 0) kz_zero<<<(n_out + 255) / 256, 256>>>(out, n_out);
        return;
    }

    k0_dict   <<<64, 256>>>(dict, vg, vb, ow);
    k1_proj   <<<dim3(8, 16, 2), 128>>>(query, key, qpe, kpe, wi);
    k1c_gram  <<<dim3(4, 16), 256>>>();
    k23_ab_max<<<dim3(64, 16), 256>>>();
    k4a_merge <<<256, 256>>>(out, n_out);
    k4b_final <<<256, 256>>>(lg, lb, out, n_out);
}